// round 9
// baseline (speedup 1.0000x reference)
#include <cuda_runtime.h>
#include <cuda_bf16.h>
#include <math.h>
#include <stdint.h>

// ---------------- problem constants ----------------
#define BB 2
#define TT 2048
#define CC 512
#define HH 8
#define DP 32
#define DH 64
#define MM (BB*TT)          // 4096 rows

// ---------------- scratch (no allocs allowed) ----------------
__device__ float g_wqk[512*512];
__device__ float g_qk [MM*512];
__device__ float g_v  [MM*CC];
__device__ float g_y  [MM*CC];
__device__ float g_h  [MM*CC];
__device__ float g_t0 [MM*CC];
__device__ float g_ln [MM*CC];
__device__ float g_t1 [MM*CC];
__device__ float g_t2 [MM*CC];
__device__ __nv_bfloat16 g_qh[BB*HH*TT*DP];
__device__ __nv_bfloat16 g_ql[BB*HH*TT*DP];
__device__ __nv_bfloat16 g_kh[BB*HH*TT*DP];
__device__ __nv_bfloat16 g_kl[BB*HH*TT*DP];
__device__ __nv_bfloat16 g_vh[MM*CC];
__device__ __nv_bfloat16 g_vl[MM*CC];

// ---------------- helpers ----------------
__device__ __forceinline__ uint32_t smem_u32(const void* p) {
    uint32_t a;
    asm("{ .reg .u64 t; cvta.to.shared.u64 t, %1; cvt.u32.u64 %0, t; }" : "=r"(a) : "l"(p));
    return a;
}
__device__ __forceinline__ void ldsm4(uint32_t* r, uint32_t addr) {
    asm volatile("ldmatrix.sync.aligned.m8n8.x4.shared.b16 {%0,%1,%2,%3}, [%4];"
        : "=r"(r[0]), "=r"(r[1]), "=r"(r[2]), "=r"(r[3]) : "r"(addr));
}
__device__ __forceinline__ void ldsm4t(uint32_t* r, uint32_t addr) {
    asm volatile("ldmatrix.sync.aligned.m8n8.x4.trans.shared.b16 {%0,%1,%2,%3}, [%4];"
        : "=r"(r[0]), "=r"(r[1]), "=r"(r[2]), "=r"(r[3]) : "r"(addr));
}
__device__ __forceinline__ void ldsm2(uint32_t* r, uint32_t addr) {
    asm volatile("ldmatrix.sync.aligned.m8n8.x2.shared.b16 {%0,%1}, [%2];"
        : "=r"(r[0]), "=r"(r[1]) : "r"(addr));
}
__device__ __forceinline__ void mma16816(float* d, const uint32_t* a, const uint32_t* b) {
    asm volatile("mma.sync.aligned.m16n8k16.row.col.f32.bf16.bf16.f32 "
        "{%0,%1,%2,%3}, {%4,%5,%6,%7}, {%8,%9}, {%0,%1,%2,%3};"
        : "+f"(d[0]), "+f"(d[1]), "+f"(d[2]), "+f"(d[3])
        : "r"(a[0]), "r"(a[1]), "r"(a[2]), "r"(a[3]), "r"(b[0]), "r"(b[1]));
}
__device__ __forceinline__ void split2(float x, float y, uint32_t& hi, uint32_t& lo) {
    __nv_bfloat162 h = __floats2bfloat162_rn(x, y);
    float2 hf = __bfloat1622float2(h);
    __nv_bfloat162 l = __floats2bfloat162_rn(x - hf.x, y - hf.y);
    hi = *(uint32_t*)&h; lo = *(uint32_t*)&l;
}
#define CP16(dst, src) \
    asm volatile("cp.async.cg.shared.global [%0], [%1], 16;" :: "r"(dst), "l"(src))
#define CP_COMMIT() asm volatile("cp.async.commit_group;" ::: "memory")
#define CP_WAIT1()  asm volatile("cp.async.wait_group 1;" ::: "memory")
#define CP_WAIT0()  asm volatile("cp.async.wait_group 0;" ::: "memory")

// ---------------- repack q/k projections into NT weight layout ----------------
__global__ void repack_kernel(const float* __restrict__ qp, const float* __restrict__ kp,
                              float* __restrict__ W) {
    int idx = blockIdx.x * 256 + threadIdx.x;
    if (idx >= 256*512) return;
    int n = idx >> 9, d = idx & 511;
    int h = n >> 5, o = n & 31;
    W[idx]            = qp[((h<<9)+d)*32 + o];
    W[(256<<9) + idx] = kp[((h<<9)+d)*32 + o];
}

// ---------------- bf16x3 mma.sync GEMM v2: 64x128 tiles, occ 2 ----------------
// mode 0: C = acc ; mode 1: C = acc + R ; mode 2: C = R + silu(acc)
#define GPAD 40
#define OFF_AH 0
#define OFF_AL 2560
#define OFF_BH 5120
#define OFF_BL 10240
#define SSTG   15360          // bf16 elems per stage (30720 B)

__global__ __launch_bounds__(256, 2)
void gemm_mma(const float* __restrict__ A, const float* __restrict__ W,
              const float* __restrict__ R, float* __restrict__ C, int mode,
              __nv_bfloat16* __restrict__ Chi, __nv_bfloat16* __restrict__ Clo) {
    extern __shared__ __align__(16) char gsm[];
    __nv_bfloat16* s = (__nv_bfloat16*)gsm;
    uint32_t sb0 = smem_u32(s);

    int tid = threadIdx.x;
    int lane = tid & 31, wid = tid >> 5;
    int wm = wid >> 2, wn = wid & 3;           // 2 x 4 warps: 32-row x 32-col warp tiles
    int row0 = blockIdx.y * 64, col0 = blockIdx.x * 128;

    float acc[2][4][4];
#pragma unroll
    for (int mi = 0; mi < 2; mi++)
#pragma unroll
        for (int ni = 0; ni < 4; ni++)
#pragma unroll
            for (int e = 0; e < 4; e++) acc[mi][ni][e] = 0.f;

    // A: 512 float4 slots (2/thread); B: 1024 slots (4/thread)
    float4 la[2], lb[4];
#pragma unroll
    for (int it = 0; it < 2; it++) {
        int slot = it * 256 + tid;
        la[it] = *(const float4*)&A[(size_t)(row0 + (slot >> 3)) * 512 + ((slot & 7) << 2)];
    }
#pragma unroll
    for (int it = 0; it < 4; it++) {
        int slot = it * 256 + tid;
        lb[it] = *(const float4*)&W[(size_t)(col0 + (slot >> 3)) * 512 + ((slot & 7) << 2)];
    }
#pragma unroll
    for (int it = 0; it < 2; it++) {
        int slot = it * 256 + tid;
        int base = (slot >> 3) * GPAD + ((slot & 7) << 2);
        uint2 h, l;
        split2(la[it].x, la[it].y, h.x, l.x); split2(la[it].z, la[it].w, h.y, l.y);
        *(uint2*)&s[OFF_AH + base] = h; *(uint2*)&s[OFF_AL + base] = l;
    }
#pragma unroll
    for (int it = 0; it < 4; it++) {
        int slot = it * 256 + tid;
        int base = (slot >> 3) * GPAD + ((slot & 7) << 2);
        uint2 h, l;
        split2(lb[it].x, lb[it].y, h.x, l.x); split2(lb[it].z, lb[it].w, h.y, l.y);
        *(uint2*)&s[OFF_BH + base] = h; *(uint2*)&s[OFF_BL + base] = l;
    }
    __syncthreads();

    for (int k = 0; k < 16; k++) {
        int cur = k & 1;
        if (k < 15) {
            int kc = (k + 1) * 32;
#pragma unroll
            for (int it = 0; it < 2; it++) {
                int slot = it * 256 + tid;
                la[it] = *(const float4*)&A[(size_t)(row0 + (slot >> 3)) * 512 + kc + ((slot & 7) << 2)];
            }
#pragma unroll
            for (int it = 0; it < 4; it++) {
                int slot = it * 256 + tid;
                lb[it] = *(const float4*)&W[(size_t)(col0 + (slot >> 3)) * 512 + kc + ((slot & 7) << 2)];
            }
        }
        uint32_t sb = sb0 + (uint32_t)cur * (SSTG * 2);
        int l16 = lane & 15;
        uint32_t arow = (uint32_t)(wm * 32 + (lane & 15)) * GPAD + (uint32_t)((lane >> 4) << 3);
        uint32_t brow = (uint32_t)(wn * 32 + (l16 & 7)) * GPAD + (uint32_t)((l16 >> 3) << 3);
#pragma unroll
        for (int ks = 0; ks < 2; ks++) {
            uint32_t ah[2][4], al[2][4], bh[4][2], bl[4][2];
#pragma unroll
            for (int mi = 0; mi < 2; mi++) {
                ldsm4(ah[mi], sb + 2 * (OFF_AH + arow + (uint32_t)(mi * 16) * GPAD + ks * 16));
                ldsm4(al[mi], sb + 2 * (OFF_AL + arow + (uint32_t)(mi * 16) * GPAD + ks * 16));
            }
#pragma unroll
            for (int ni = 0; ni < 4; ni++) {
                uint32_t ba = sb + 2 * (brow + (uint32_t)(ni * 8) * GPAD + ks * 16);
                ldsm2(bh[ni], ba + 2 * OFF_BH);
                ldsm2(bl[ni], ba + 2 * OFF_BL);
            }
#pragma unroll
            for (int mi = 0; mi < 2; mi++)
#pragma unroll
                for (int ni = 0; ni < 4; ni++) {
                    mma16816(acc[mi][ni], ah[mi], bh[ni]);
                    mma16816(acc[mi][ni], ah[mi], bl[ni]);
                    mma16816(acc[mi][ni], al[mi], bh[ni]);
                }
        }
        if (k < 15) {
            __nv_bfloat16* sn = s + (size_t)((k + 1) & 1) * SSTG;
#pragma unroll
            for (int it = 0; it < 2; it++) {
                int slot = it * 256 + tid;
                int base = (slot >> 3) * GPAD + ((slot & 7) << 2);
                uint2 h, l;
                split2(la[it].x, la[it].y, h.x, l.x); split2(la[it].z, la[it].w, h.y, l.y);
                *(uint2*)&sn[OFF_AH + base] = h; *(uint2*)&sn[OFF_AL + base] = l;
            }
#pragma unroll
            for (int it = 0; it < 4; it++) {
                int slot = it * 256 + tid;
                int base = (slot >> 3) * GPAD + ((slot & 7) << 2);
                uint2 h, l;
                split2(lb[it].x, lb[it].y, h.x, l.x); split2(lb[it].z, lb[it].w, h.y, l.y);
                *(uint2*)&sn[OFF_BH + base] = h; *(uint2*)&sn[OFF_BL + base] = l;
            }
        }
        __syncthreads();
    }

    int gid = lane >> 2, tig = lane & 3;
#pragma unroll
    for (int mi = 0; mi < 2; mi++) {
#pragma unroll
        for (int ni = 0; ni < 4; ni++) {
            int rg = row0 + wm * 32 + mi * 16 + gid;
            int cg = col0 + wn * 32 + ni * 8 + tig * 2;
#pragma unroll
            for (int half = 0; half < 2; half++) {
                int r = rg + half * 8;
                float vx = acc[mi][ni][half * 2], vy = acc[mi][ni][half * 2 + 1];
                size_t gi = (size_t)r * 512 + cg;
                if (mode == 1) {
                    float2 rv = *(const float2*)&R[gi];
                    vx += rv.x; vy += rv.y;
                } else if (mode == 2) {
                    float2 rv = *(const float2*)&R[gi];
                    vx = rv.x + vx / (1.f + __expf(-vx));
                    vy = rv.y + vy / (1.f + __expf(-vy));
                }
                float2 ov; ov.x = vx; ov.y = vy;
                *(float2*)&C[gi] = ov;
                if (Chi) {
                    uint32_t hh, ll;
                    split2(vx, vy, hh, ll);
                    *(uint32_t*)&Chi[gi] = hh;
                    *(uint32_t*)&Clo[gi] = ll;
                }
            }
        }
    }
}

// ---------------- RoPE + gain (+ scale folded into q), bf16 hi/lo outputs ----------------
__global__ void rope_kernel(const float* __restrict__ QK, const float* __restrict__ gain,
                            __nv_bfloat16* __restrict__ Qh, __nv_bfloat16* __restrict__ Ql,
                            __nv_bfloat16* __restrict__ Kh, __nv_bfloat16* __restrict__ Kl) {
    int bt = blockIdx.x;
    int t  = bt & (TT - 1);
    int b  = bt >> 11;
    int tid = threadIdx.x;
    int h = tid >> 4, i = tid & 15;
    float freq = powf(10000.f, -(float)i * (1.f / 16.f));
    float ang  = (float)t * freq;
    float c = cosf(ang), s = sinf(ang);
    const float* rowq = QK + (size_t)bt * 512 + h * 32;
    const float* rowk = rowq + 256;
    float g  = gain[h] * 0.17677669529663687f;
    float q1 = rowq[i], q2 = rowq[i + 16];
    float k1 = rowk[i], k2 = rowk[i + 16];
    float qa = (q1 * c - q2 * s) * g;
    float qb = (q2 * c + q1 * s) * g;
    float ka = (k1 * c - k2 * s);
    float kb = (k2 * c + k1 * s);
    size_t base = ((size_t)(b * HH + h) * TT + t) * DP;
    __nv_bfloat16 hh;
    hh = __float2bfloat16_rn(qa); Qh[base + i]      = hh; Ql[base + i]      = __float2bfloat16_rn(qa - __bfloat162float(hh));
    hh = __float2bfloat16_rn(qb); Qh[base + i + 16] = hh; Ql[base + i + 16] = __float2bfloat16_rn(qb - __bfloat162float(hh));
    hh = __float2bfloat16_rn(ka); Kh[base + i]      = hh; Kl[base + i]      = __float2bfloat16_rn(ka - __bfloat162float(hh));
    hh = __float2bfloat16_rn(kb); Kh[base + i + 16] = hh; Kl[base + i + 16] = __float2bfloat16_rn(kb - __bfloat162float(hh));
}

// ---------------- flash attention: pre-split bf16 + cp.async pipeline, occ 2 ----------------
#define FKP 40
#define FVP 72
#define SKH 0
#define SKL 2560
#define SVH 5120
#define SVL 9728
#define FSTG 14336

__global__ __launch_bounds__(256, 2)
void flash_mma(const __nv_bfloat16* __restrict__ Qh, const __nv_bfloat16* __restrict__ Ql,
               const __nv_bfloat16* __restrict__ Kh, const __nv_bfloat16* __restrict__ Kl,
               const __nv_bfloat16* __restrict__ Vh, const __nv_bfloat16* __restrict__ Vl,
               const float* __restrict__ V, float* __restrict__ Y) {
    extern __shared__ __align__(16) __nv_bfloat16 fs[];
    uint32_t sb = smem_u32(fs);

    int b = blockIdx.z, h = blockIdx.y;
    int qt = (int)gridDim.x - 1 - (int)blockIdx.x;     // heavy blocks first
    int tid = threadIdx.x, lane = tid & 31, wid = tid >> 5;
    int gid = lane >> 2, tig = lane & 3;
    int qrow0 = qt * 128;

    size_t bh = (size_t)(b * HH + h) * TT;
    const __nv_bfloat16* Khg = Kh + bh * DP;
    const __nv_bfloat16* Klg = Kl + bh * DP;
    const __nv_bfloat16* Vhg = Vh + (size_t)b * TT * CC + h * DH;
    const __nv_bfloat16* Vlg = Vl + (size_t)b * TT * CC + h * DH;
    const float* Vb = V + (size_t)b * TT * CC + h * DH;

    // ---- stage Q (pre-split bf16) into stage-0 smem, grab fragments ----
#pragma unroll
    for (int it = 0; it < 4; it++) {
        int c = it * 256 + tid;
        int row = (c & 511) >> 2, col = (c & 3) << 3;
        const __nv_bfloat16* src = (c < 512) ? (Qh + (bh + qrow0 + row) * DP + col)
                                             : (Ql + (bh + qrow0 + row) * DP + col);
        uint32_t doff = (c < 512) ? (uint32_t)(row * FKP + col) : (uint32_t)(5120 + row * FKP + col);
        *(uint4*)&fs[doff] = *(const uint4*)src;
    }
    __syncthreads();
    uint32_t qfh[2][4], qfl[2][4];
    {
        uint32_t arow = (uint32_t)(wid * 16 + (lane & 15)) * FKP + (uint32_t)((lane >> 4) << 3);
#pragma unroll
        for (int ks = 0; ks < 2; ks++) {
            ldsm4(qfh[ks], sb + 2 * (arow + ks * 16));
            ldsm4(qfl[ks], sb + 2 * (5120 + arow + ks * 16));
        }
    }
    __syncthreads();

    float m0 = -1e30f, m1 = -1e30f, l0 = 0.f, l1 = 0.f;
    float o[8][4];
#pragma unroll
    for (int nt = 0; nt < 8; nt++)
#pragma unroll
        for (int e = 0; e < 4; e++) o[nt][e] = 0.f;

    int wmax = qrow0 + wid * 16 + 15;
    int ntiles = 2 * qt + 2;

    auto issue = [&](int t, int s) {
        uint32_t st = sb + 2 * (uint32_t)(s * FSTG);
        int j0 = t * 64;
#pragma unroll
        for (int it = 0; it < 6; it++) {
            int c = it * 256 + tid;
            if (c < 512) {
                int row = (c & 255) >> 2, col = (c & 3) << 3;
                const __nv_bfloat16* src = (c < 256) ? (Khg + (size_t)(j0 + row) * DP + col)
                                                     : (Klg + (size_t)(j0 + row) * DP + col);
                uint32_t doff = (c < 256) ? (uint32_t)(SKH + row * FKP + col)
                                          : (uint32_t)(SKL + row * FKP + col);
                CP16(st + 2 * doff, src);
            } else {
                int cc = c - 512;
                int row = (cc & 511) >> 3, col = (cc & 7) << 3;
                const __nv_bfloat16* src = (cc < 512) ? (Vhg + (size_t)(j0 + row) * CC + col)
                                                      : (Vlg + (size_t)(j0 + row) * CC + col);
                uint32_t doff = (cc < 512) ? (uint32_t)(SVH + row * FVP + col)
                                           : (uint32_t)(SVL + row * FVP + col);
                CP16(st + 2 * doff, src);
            }
        }
    };

    issue(0, 0);
    CP_COMMIT();

    for (int t = 0; t < ntiles; t++) {
        int s = t & 1;
        if (t + 1 < ntiles) { issue(t + 1, s ^ 1); CP_COMMIT(); CP_WAIT1(); }
        else                { CP_WAIT0(); }
        __syncthreads();

        int j0 = t * 64;
        uint32_t stg = sb + 2 * (uint32_t)(s * FSTG);
        if (j0 <= wmax) {
            // ---- QK^T ----
            float sc[8][4];
#pragma unroll
            for (int nt = 0; nt < 8; nt++)
#pragma unroll
                for (int e = 0; e < 4; e++) sc[nt][e] = 0.f;
            uint32_t kbase = (uint32_t)(lane & 7) * FKP + (uint32_t)(((lane >> 3) & 3) << 3);
#pragma unroll
            for (int nt = 0; nt < 8; nt++) {
                uint32_t kbh[4], kbl[4];
                uint32_t ka = stg + 2 * (kbase + (uint32_t)(nt * 8) * FKP);
                ldsm4(kbh, ka + 2 * SKH);
                ldsm4(kbl, ka + 2 * SKL);
                mma16816(sc[nt], qfh[0], kbh);
                mma16816(sc[nt], qfh[1], kbh + 2);
                mma16816(sc[nt], qfh[0], kbl);
                mma16816(sc[nt], qfh[1], kbl + 2);
                mma16816(sc[nt], qfl[0], kbh);
                mma16816(sc[nt], qfl[1], kbh + 2);
            }
            // ---- causal mask ----
            if (j0 + 63 > qrow0 + wid * 16) {
                int r0 = qrow0 + wid * 16 + gid, r1 = r0 + 8;
#pragma unroll
                for (int nt = 0; nt < 8; nt++) {
                    int c = j0 + nt * 8 + tig * 2;
                    if (c > r0)     sc[nt][0] = -1e30f;
                    if (c + 1 > r0) sc[nt][1] = -1e30f;
                    if (c > r1)     sc[nt][2] = -1e30f;
                    if (c + 1 > r1) sc[nt][3] = -1e30f;
                }
            }
            // ---- online softmax ----
            float mx0 = -1e30f, mx1 = -1e30f;
#pragma unroll
            for (int nt = 0; nt < 8; nt++) {
                mx0 = fmaxf(mx0, fmaxf(sc[nt][0], sc[nt][1]));
                mx1 = fmaxf(mx1, fmaxf(sc[nt][2], sc[nt][3]));
            }
            mx0 = fmaxf(mx0, __shfl_xor_sync(~0u, mx0, 1));
            mx0 = fmaxf(mx0, __shfl_xor_sync(~0u, mx0, 2));
            mx1 = fmaxf(mx1, __shfl_xor_sync(~0u, mx1, 1));
            mx1 = fmaxf(mx1, __shfl_xor_sync(~0u, mx1, 2));
            float mn0 = fmaxf(m0, mx0), mn1 = fmaxf(m1, mx1);
            float cr0 = __expf(m0 - mn0), cr1 = __expf(m1 - mn1);
            m0 = mn0; m1 = mn1;
            float ls0 = 0.f, ls1 = 0.f;
#pragma unroll
            for (int nt = 0; nt < 8; nt++) {
                sc[nt][0] = __expf(sc[nt][0] - m0);
                sc[nt][1] = __expf(sc[nt][1] - m0);
                sc[nt][2] = __expf(sc[nt][2] - m1);
                sc[nt][3] = __expf(sc[nt][3] - m1);
                ls0 += sc[nt][0] + sc[nt][1];
                ls1 += sc[nt][2] + sc[nt][3];
            }
            l0 = l0 * cr0 + ls0;
            l1 = l1 * cr1 + ls1;
#pragma unroll
            for (int nt = 0; nt < 8; nt++) {
                o[nt][0] *= cr0; o[nt][1] *= cr0;
                o[nt][2] *= cr1; o[nt][3] *= cr1;
            }
            // ---- P @ V ----
            uint32_t vbase = (uint32_t)(lane & 15) * FVP + (uint32_t)((lane >> 4) << 3);
#pragma unroll
            for (int kk = 0; kk < 4; kk++) {
                uint32_t ah[4], al[4];
                split2(sc[2*kk][0],   sc[2*kk][1],   ah[0], al[0]);
                split2(sc[2*kk][2],   sc[2*kk][3],   ah[1], al[1]);
                split2(sc[2*kk+1][0], sc[2*kk+1][1], ah[2], al[2]);
                split2(sc[2*kk+1][2], sc[2*kk+1][3], ah[3], al[3]);
#pragma unroll
                for (int nv = 0; nv < 4; nv++) {
                    uint32_t vbh[4], vbl[4];
                    uint32_t va = stg + 2 * (vbase + (uint32_t)(kk * 16) * FVP + (uint32_t)(nv * 16));
                    ldsm4t(vbh, va + 2 * SVH);
                    ldsm4t(vbl, va + 2 * SVL);
                    mma16816(o[2*nv],     ah, vbh);
                    mma16816(o[2*nv + 1], ah, vbh + 2);
                    mma16816(o[2*nv],     ah, vbl);
                    mma16816(o[2*nv + 1], ah, vbl + 2);
                    mma16816(o[2*nv],     al, vbh);
                    mma16816(o[2*nv + 1], al, vbh + 2);
                }
            }
        }
        __syncthreads();
    }

    // ---- finalize ----
    l0 += __shfl_xor_sync(~0u, l0, 1); l0 += __shfl_xor_sync(~0u, l0, 2);
    l1 += __shfl_xor_sync(~0u, l1, 1); l1 += __shfl_xor_sync(~0u, l1, 2);
    float inv0 = 1.f / l0, inv1 = 1.f / l1;
#pragma unroll
    for (int nt = 0; nt < 8; nt++) {
        o[nt][0] *= inv0; o[nt][1] *= inv0;
        o[nt][2] *= inv1; o[nt][3] *= inv1;
    }
    int i0 = qrow0 + wid * 16 + gid, i1 = i0 + 8;
    float dot0 = 0.f, n20 = 0.f, dot1 = 0.f, n21 = 0.f;
#pragma unroll
    for (int nt = 0; nt < 8; nt++) {
        int d = nt * 8 + tig * 2;
        float2 v0 = *(const float2*)&Vb[(size_t)i0 * CC + d];
        float2 v1 = *(const float2*)&Vb[(size_t)i1 * CC + d];
        dot0 += o[nt][0] * v0.x + o[nt][1] * v0.y;
        n20  += v0.x * v0.x + v0.y * v0.y;
        dot1 += o[nt][2] * v1.x + o[nt][3] * v1.y;
        n21  += v1.x * v1.x + v1.y * v1.y;
    }
    dot0 += __shfl_xor_sync(~0u, dot0, 1); dot0 += __shfl_xor_sync(~0u, dot0, 2);
    n20  += __shfl_xor_sync(~0u, n20, 1);  n20  += __shfl_xor_sync(~0u, n20, 2);
    dot1 += __shfl_xor_sync(~0u, dot1, 1); dot1 += __shfl_xor_sync(~0u, dot1, 2);
    n21  += __shfl_xor_sync(~0u, n21, 1);  n21  += __shfl_xor_sync(~0u, n21, 2);
    float nr0 = fmaxf(sqrtf(n20), 1e-12f);
    float nr1 = fmaxf(sqrtf(n21), 1e-12f);
    dot0 /= (nr0 * nr0);
    dot1 /= (nr1 * nr1);
    float* Y0 = Y + (size_t)(b * TT + i0) * CC + h * DH;
    float* Y1 = Y + (size_t)(b * TT + i1) * CC + h * DH;
#pragma unroll
    for (int nt = 0; nt < 8; nt++) {
        int d = nt * 8 + tig * 2;
        float2 v0 = *(const float2*)&Vb[(size_t)i0 * CC + d];
        float2 v1 = *(const float2*)&Vb[(size_t)i1 * CC + d];
        float2 y0, y1;
        y0.x = o[nt][0] - dot0 * v0.x; y0.y = o[nt][1] - dot0 * v0.y;
        y1.x = o[nt][2] - dot1 * v1.x; y1.y = o[nt][3] - dot1 * v1.y;
        *(float2*)&Y0[d] = y0;
        *(float2*)&Y1[d] = y1;
    }
}

// ---------------- layernorm (row of 512) ----------------
__global__ void ln_kernel(const float* __restrict__ X, const float* __restrict__ g,
                          const float* __restrict__ bta, float* __restrict__ O) {
    int row = blockIdx.x;
    int t = threadIdx.x;
    __shared__ float red[4], red2[4];
    const float* xp = X + (size_t)row * 512;
    float4 v = *(const float4*)&xp[t * 4];
    float s = v.x + v.y + v.z + v.w;
#pragma unroll
    for (int off = 16; off; off >>= 1) s += __shfl_xor_sync(~0u, s, off);
    if ((t & 31) == 0) red[t >> 5] = s;
    __syncthreads();
    float mean = (red[0] + red[1] + red[2] + red[3]) * (1.f / 512.f);
    float dx = v.x - mean, dy = v.y - mean, dz = v.z - mean, dw = v.w - mean;
    float s2 = dx*dx + dy*dy + dz*dz + dw*dw;
#pragma unroll
    for (int off = 16; off; off >>= 1) s2 += __shfl_xor_sync(~0u, s2, off);
    if ((t & 31) == 0) red2[t >> 5] = s2;
    __syncthreads();
    float var = (red2[0] + red2[1] + red2[2] + red2[3]) * (1.f / 512.f);
    float rsv = rsqrtf(var + 1e-5f);
    float4 gg = *(const float4*)&g[t * 4];
    float4 bb = *(const float4*)&bta[t * 4];
    float4 ov;
    ov.x = dx * rsv * gg.x + bb.x;
    ov.y = dy * rsv * gg.y + bb.y;
    ov.z = dz * rsv * gg.z + bb.z;
    ov.w = dw * rsv * gg.w + bb.w;
    *(float4*)&O[(size_t)row * 512 + t * 4] = ov;
}

// ---------------- rms + out-proj (32) + tanh/temp ----------------
__global__ void final_kernel(const float* __restrict__ X, const float* __restrict__ Wout,
                             const float* __restrict__ ct, float* __restrict__ Z) {
    int row = blockIdx.x;
    int t = threadIdx.x;
    __shared__ __align__(16) float xs[512];
    __shared__ float red[8];
    __shared__ float pm[32][9];
    const float* xp = X + (size_t)row * 512;
    float2 v = *(const float2*)&xp[t * 2];
    float s2 = v.x * v.x + v.y * v.y;
#pragma unroll
    for (int off = 16; off; off >>= 1) s2 += __shfl_xor_sync(~0u, s2, off);
    if ((t & 31) == 0) red[t >> 5] = s2;
    __syncthreads();
    float tot = 0.f;
#pragma unroll
    for (int w = 0; w < 8; w++) tot += red[w];
    float rs = rsqrtf(tot * (1.f / 512.f) + 1e-6f);
    xs[t*2] = v.x * rs; xs[t*2+1] = v.y * rs;
    __syncthreads();
    int mi = t >> 3, seg = t & 7;
    const float* wrow = Wout + mi * 512 + seg * 64;
    const float* xseg = xs + seg * 64;
    float acc = 0.f;
#pragma unroll
    for (int d = 0; d < 64; d += 4) {
        float4 wv = *(const float4*)&wrow[d];
        acc += xseg[d]*wv.x + xseg[d+1]*wv.y + xseg[d+2]*wv.z + xseg[d+3]*wv.w;
    }
    pm[mi][seg] = acc;
    __syncthreads();
    if (t < 32) {
        float a = 0.f;
#pragma unroll
        for (int sgi = 0; sgi < 8; sgi++) a += pm[t][sgi];
        float cv = ct[t];
        float sp = (cv > 20.f) ? cv : log1pf(expf(cv));
        Z[(size_t)row * 32 + t] = tanhf(a / (sp + 1e-4f));
    }
}

// ---------------- launch ----------------
extern "C" void kernel_launch(void* const* d_in, const int* in_sizes, int n_in,
                              void* d_out, int out_size) {
    const float* x       = (const float*)d_in[0];
    const float* q_projs = (const float*)d_in[1];
    const float* k_projs = (const float*)d_in[2];
    const float* w_v     = (const float*)d_in[3];
    const float* w_proj  = (const float*)d_in[4];
    const float* q_gain  = (const float*)d_in[5];
    const float* enc_w0  = (const float*)d_in[6];
    const float* ln1g    = (const float*)d_in[7];
    const float* ln1b    = (const float*)d_in[8];
    const float* enc_w1  = (const float*)d_in[9];
    const float* ln2g    = (const float*)d_in[10];
    const float* ln2b    = (const float*)d_in[11];
    const float* enc_w2  = (const float*)d_in[12];
    const float* enc_wo  = (const float*)d_in[13];
    const float* ctemp   = (const float*)d_in[14];
    float* out = (float*)d_out;

    float *p_wqk, *p_qk, *p_v, *p_y, *p_h, *p_t0, *p_ln, *p_t1, *p_t2;
    __nv_bfloat16 *p_qh, *p_ql, *p_kh, *p_kl, *p_vh, *p_vl;
    cudaGetSymbolAddress((void**)&p_wqk, g_wqk);
    cudaGetSymbolAddress((void**)&p_qk,  g_qk);
    cudaGetSymbolAddress((void**)&p_v,   g_v);
    cudaGetSymbolAddress((void**)&p_y,   g_y);
    cudaGetSymbolAddress((void**)&p_h,   g_h);
    cudaGetSymbolAddress((void**)&p_t0,  g_t0);
    cudaGetSymbolAddress((void**)&p_ln,  g_ln);
    cudaGetSymbolAddress((void**)&p_t1,  g_t1);
    cudaGetSymbolAddress((void**)&p_t2,  g_t2);
    cudaGetSymbolAddress((void**)&p_qh,  g_qh);
    cudaGetSymbolAddress((void**)&p_ql,  g_ql);
    cudaGetSymbolAddress((void**)&p_kh,  g_kh);
    cudaGetSymbolAddress((void**)&p_kl,  g_kl);
    cudaGetSymbolAddress((void**)&p_vh,  g_vh);
    cudaGetSymbolAddress((void**)&p_vl,  g_vl);

    const int GEMM_SMEM  = 2 * SSTG * 2;   // 61440 B (two stages)
    const int FLASH_SMEM = 2 * FSTG * 2;   // 57344 B
    cudaFuncSetAttribute(gemm_mma,  cudaFuncAttributeMaxDynamicSharedMemorySize, GEMM_SMEM);
    cudaFuncSetAttribute(flash_mma, cudaFuncAttributeMaxDynamicSharedMemorySize, FLASH_SMEM);

    dim3 ggrid(512 / 128, MM / 64);   // (4, 64) = 256 CTAs

    repack_kernel<<<512, 256>>>(q_projs, k_projs, p_wqk);
    gemm_mma<<<ggrid, 256, GEMM_SMEM>>>(x, p_wqk, nullptr, p_qk, 0, nullptr, nullptr);
    rope_kernel<<<MM, 128>>>(p_qk, q_gain, p_qh, p_ql, p_kh, p_kl);
    gemm_mma<<<ggrid, 256, GEMM_SMEM>>>(x, w_v, nullptr, p_v, 0, p_vh, p_vl);
    flash_mma<<<dim3(TT / 128, HH, BB), 256, FLASH_SMEM>>>(p_qh, p_ql, p_kh, p_kl,
                                                           p_vh, p_vl, p_v, p_y);
    gemm_mma<<<ggrid, 256, GEMM_SMEM>>>(p_y, w_proj, x, p_h, 1, nullptr, nullptr);
    gemm_mma<<<ggrid, 256, GEMM_SMEM>>>(p_h, enc_w0, nullptr, p_t0, 0, nullptr, nullptr);
    ln_kernel<<<MM, 128>>>(p_t0, ln1g, ln1b, p_ln);
    gemm_mma<<<ggrid, 256, GEMM_SMEM>>>(p_ln, enc_w1, p_h, p_t1, 2, nullptr, nullptr);
    ln_kernel<<<MM, 128>>>(p_t1, ln2g, ln2b, p_ln);
    gemm_mma<<<ggrid, 256, GEMM_SMEM>>>(p_ln, enc_w2, p_t1, p_t2, 2, nullptr, nullptr);
    final_kernel<<<MM, 256>>>(p_t2, enc_wo, ctemp, out);
}

// round 10
// speedup vs baseline: 1.0072x; 1.0072x over previous
#include <cuda_runtime.h>
#include <cuda_bf16.h>
#include <math.h>
#include <stdint.h>

// ---------------- problem constants ----------------
#define BB 2
#define TT 2048
#define CC 512
#define HH 8
#define DP 32
#define DH 64
#define MM (BB*TT)          // 4096 rows

// ---------------- scratch (no allocs allowed) ----------------
__device__ float g_qk [MM*512];
__device__ float g_v  [MM*CC];
__device__ float g_h  [MM*CC];
__device__ float g_t0 [MM*CC];
__device__ float g_t1 [MM*CC];
__device__ float g_t2 [MM*CC];
__device__ __nv_bfloat16 g_xh [MM*CC],  g_xl [MM*CC];
__device__ __nv_bfloat16 g_wqkh[512*512], g_wqkl[512*512];
__device__ __nv_bfloat16 g_wvh[512*512],  g_wvl[512*512];
__device__ __nv_bfloat16 g_wph[512*512],  g_wpl[512*512];
__device__ __nv_bfloat16 g_w0h[512*512],  g_w0l[512*512];
__device__ __nv_bfloat16 g_w1h[512*512],  g_w1l[512*512];
__device__ __nv_bfloat16 g_w2h[512*512],  g_w2l[512*512];
__device__ __nv_bfloat16 g_qh[BB*HH*TT*DP], g_ql[BB*HH*TT*DP];
__device__ __nv_bfloat16 g_kh[BB*HH*TT*DP], g_kl[BB*HH*TT*DP];
__device__ __nv_bfloat16 g_vh[MM*CC], g_vl[MM*CC];
__device__ __nv_bfloat16 g_yh[MM*CC], g_yl[MM*CC];
__device__ __nv_bfloat16 g_hh[MM*CC], g_hl[MM*CC];
__device__ __nv_bfloat16 g_lnh[MM*CC], g_lnl[MM*CC];

// ---------------- helpers ----------------
__device__ __forceinline__ uint32_t smem_u32(const void* p) {
    uint32_t a;
    asm("{ .reg .u64 t; cvta.to.shared.u64 t, %1; cvt.u32.u64 %0, t; }" : "=r"(a) : "l"(p));
    return a;
}
__device__ __forceinline__ void ldsm4(uint32_t* r, uint32_t addr) {
    asm volatile("ldmatrix.sync.aligned.m8n8.x4.shared.b16 {%0,%1,%2,%3}, [%4];"
        : "=r"(r[0]), "=r"(r[1]), "=r"(r[2]), "=r"(r[3]) : "r"(addr));
}
__device__ __forceinline__ void ldsm4t(uint32_t* r, uint32_t addr) {
    asm volatile("ldmatrix.sync.aligned.m8n8.x4.trans.shared.b16 {%0,%1,%2,%3}, [%4];"
        : "=r"(r[0]), "=r"(r[1]), "=r"(r[2]), "=r"(r[3]) : "r"(addr));
}
__device__ __forceinline__ void ldsm2(uint32_t* r, uint32_t addr) {
    asm volatile("ldmatrix.sync.aligned.m8n8.x2.shared.b16 {%0,%1}, [%2];"
        : "=r"(r[0]), "=r"(r[1]) : "r"(addr));
}
__device__ __forceinline__ void mma16816(float* d, const uint32_t* a, const uint32_t* b) {
    asm volatile("mma.sync.aligned.m16n8k16.row.col.f32.bf16.bf16.f32 "
        "{%0,%1,%2,%3}, {%4,%5,%6,%7}, {%8,%9}, {%0,%1,%2,%3};"
        : "+f"(d[0]), "+f"(d[1]), "+f"(d[2]), "+f"(d[3])
        : "r"(a[0]), "r"(a[1]), "r"(a[2]), "r"(a[3]), "r"(b[0]), "r"(b[1]));
}
__device__ __forceinline__ void split2(float x, float y, uint32_t& hi, uint32_t& lo) {
    __nv_bfloat162 h = __floats2bfloat162_rn(x, y);
    float2 hf = __bfloat1622float2(h);
    __nv_bfloat162 l = __floats2bfloat162_rn(x - hf.x, y - hf.y);
    hi = *(uint32_t*)&h; lo = *(uint32_t*)&l;
}
#define CP16(dst, src) \
    asm volatile("cp.async.cg.shared.global [%0], [%1], 16;" :: "r"(dst), "l"(src))
#define CP_COMMIT() asm volatile("cp.async.commit_group;" ::: "memory")
#define CP_WAIT1()  asm volatile("cp.async.wait_group 1;" ::: "memory")
#define CP_WAIT0()  asm volatile("cp.async.wait_group 0;" ::: "memory")

// ---------------- fp32 -> bf16 hi/lo split (elementwise) ----------------
__global__ void split_kernel(const float* __restrict__ X,
                             __nv_bfloat16* __restrict__ H, __nv_bfloat16* __restrict__ L,
                             int n4) {
    int i = blockIdx.x * 256 + threadIdx.x;
    if (i >= n4) return;
    float4 v = ((const float4*)X)[i];
    uint2 h, l;
    split2(v.x, v.y, h.x, l.x); split2(v.z, v.w, h.y, l.y);
    ((uint2*)H)[i] = h; ((uint2*)L)[i] = l;
}

// ---------------- repack q/k projections + split to hi/lo ----------------
__global__ void repack_kernel(const float* __restrict__ qp, const float* __restrict__ kp,
                              __nv_bfloat16* __restrict__ Wh, __nv_bfloat16* __restrict__ Wl) {
    int idx = blockIdx.x * 256 + threadIdx.x;
    if (idx >= 256*512) return;
    int n = idx >> 9, d = idx & 511;
    int h = n >> 5, o = n & 31;
    float vq = qp[((h<<9)+d)*32 + o];
    float vk = kp[((h<<9)+d)*32 + o];
    __nv_bfloat16 hh;
    hh = __float2bfloat16_rn(vq);
    Wh[idx] = hh; Wl[idx] = __float2bfloat16_rn(vq - __bfloat162float(hh));
    hh = __float2bfloat16_rn(vk);
    Wh[(256<<9) + idx] = hh; Wl[(256<<9) + idx] = __float2bfloat16_rn(vk - __bfloat162float(hh));
}

// ---------------- pure-bf16 mma.sync GEMM: 128x128 tile, cp.async 2-stage ----------------
// mode 0: C = acc ; mode 1: C = acc + R ; mode 2: C = R + silu(acc)
#define GPAD 40
#define OFF_AH 0
#define OFF_AL 5120
#define OFF_BH 10240
#define OFF_BL 15360
#define GSTG   20480          // bf16 elems per stage (40960 B)

__global__ __launch_bounds__(256, 1)
void gemm_bf16(const __nv_bfloat16* __restrict__ Ah, const __nv_bfloat16* __restrict__ Al,
               const __nv_bfloat16* __restrict__ Bh, const __nv_bfloat16* __restrict__ Bl,
               const float* __restrict__ R, float* __restrict__ C, int mode,
               __nv_bfloat16* __restrict__ Chi, __nv_bfloat16* __restrict__ Clo) {
    extern __shared__ __align__(16) __nv_bfloat16 s[];
    uint32_t sb0 = smem_u32(s);

    int tid = threadIdx.x;
    int lane = tid & 31, wid = tid >> 5;
    int wm = wid >> 2, wn = wid & 3;           // 2 x 4 warps (64 x 32 tiles)
    int row0 = blockIdx.y * 128, col0 = blockIdx.x * 128;

    float acc[4][4][4];
#pragma unroll
    for (int mi = 0; mi < 4; mi++)
#pragma unroll
        for (int ni = 0; ni < 4; ni++)
#pragma unroll
            for (int e = 0; e < 4; e++) acc[mi][ni][e] = 0.f;

    // issue one k-chunk (32 cols) into stage st: 4 matrices x 512 16B-chunks
    auto issue = [&](int k, int st) {
        uint32_t s0 = sb0 + 2 * (uint32_t)(st * GSTG);
        int kc = k * 32;
#pragma unroll
        for (int it = 0; it < 8; it++) {
            int mat = it >> 1;                       // 0=Ah 1=Al 2=Bh 3=Bl
            int cc  = ((it & 1) << 8) + tid;         // 0..511
            int r   = cc >> 2, col = (cc & 3) << 3;
            const __nv_bfloat16* g =
                (mat == 0) ? Ah + (size_t)(row0 + r) * 512 + kc + col :
                (mat == 1) ? Al + (size_t)(row0 + r) * 512 + kc + col :
                (mat == 2) ? Bh + (size_t)(col0 + r) * 512 + kc + col :
                             Bl + (size_t)(col0 + r) * 512 + kc + col;
            CP16(s0 + 2 * (uint32_t)(mat * 5120 + r * GPAD + col), g);
        }
    };

    issue(0, 0);
    CP_COMMIT();

    for (int k = 0; k < 16; k++) {
        int cur = k & 1;
        if (k < 15) { issue(k + 1, cur ^ 1); CP_COMMIT(); CP_WAIT1(); }
        else        { CP_WAIT0(); }
        __syncthreads();

        uint32_t sb = sb0 + (uint32_t)cur * (GSTG * 2);
        int l16 = lane & 15;
        uint32_t arow = (uint32_t)(wm * 64 + (lane & 15)) * GPAD + (uint32_t)((lane >> 4) << 3);
        uint32_t brow = (uint32_t)(wn * 32 + (l16 & 7)) * GPAD + (uint32_t)((l16 >> 3) << 3);
#pragma unroll
        for (int ks = 0; ks < 2; ks++) {
            uint32_t a[4][4], bh[4][2], bl[4][2];
#pragma unroll
            for (int mi = 0; mi < 4; mi++)
                ldsm4(a[mi], sb + 2 * (OFF_AH + arow + (uint32_t)(mi * 16) * GPAD + ks * 16));
#pragma unroll
            for (int ni = 0; ni < 4; ni++) {
                uint32_t ba = sb + 2 * (brow + (uint32_t)(ni * 8) * GPAD + ks * 16);
                ldsm2(bh[ni], ba + 2 * OFF_BH);
                ldsm2(bl[ni], ba + 2 * OFF_BL);
            }
#pragma unroll
            for (int mi = 0; mi < 4; mi++)
#pragma unroll
                for (int ni = 0; ni < 4; ni++) mma16816(acc[mi][ni], a[mi], bh[ni]);
#pragma unroll
            for (int mi = 0; mi < 4; mi++)
#pragma unroll
                for (int ni = 0; ni < 4; ni++) mma16816(acc[mi][ni], a[mi], bl[ni]);
#pragma unroll
            for (int mi = 0; mi < 4; mi++)
                ldsm4(a[mi], sb + 2 * (OFF_AL + arow + (uint32_t)(mi * 16) * GPAD + ks * 16));
#pragma unroll
            for (int mi = 0; mi < 4; mi++)
#pragma unroll
                for (int ni = 0; ni < 4; ni++) mma16816(acc[mi][ni], a[mi], bh[ni]);
        }
        __syncthreads();
    }

    int gid = lane >> 2, tig = lane & 3;
#pragma unroll
    for (int mi = 0; mi < 4; mi++) {
#pragma unroll
        for (int ni = 0; ni < 4; ni++) {
            int rg = row0 + wm * 64 + mi * 16 + gid;
            int cg = col0 + wn * 32 + ni * 8 + tig * 2;
#pragma unroll
            for (int half = 0; half < 2; half++) {
                int r = rg + half * 8;
                float vx = acc[mi][ni][half * 2], vy = acc[mi][ni][half * 2 + 1];
                size_t gi = (size_t)r * 512 + cg;
                if (mode == 1) {
                    float2 rv = *(const float2*)&R[gi];
                    vx += rv.x; vy += rv.y;
                } else if (mode == 2) {
                    float2 rv = *(const float2*)&R[gi];
                    vx = rv.x + vx / (1.f + __expf(-vx));
                    vy = rv.y + vy / (1.f + __expf(-vy));
                }
                float2 ov; ov.x = vx; ov.y = vy;
                *(float2*)&C[gi] = ov;
                if (Chi) {
                    uint32_t hh, ll;
                    split2(vx, vy, hh, ll);
                    *(uint32_t*)&Chi[gi] = hh;
                    *(uint32_t*)&Clo[gi] = ll;
                }
            }
        }
    }
}

// ---------------- RoPE + gain (+ scale folded into q), bf16 hi/lo outputs ----------------
__global__ void rope_kernel(const float* __restrict__ QK, const float* __restrict__ gain,
                            __nv_bfloat16* __restrict__ Qh, __nv_bfloat16* __restrict__ Ql,
                            __nv_bfloat16* __restrict__ Kh, __nv_bfloat16* __restrict__ Kl) {
    int bt = blockIdx.x;
    int t  = bt & (TT - 1);
    int b  = bt >> 11;
    int tid = threadIdx.x;
    int h = tid >> 4, i = tid & 15;
    float freq = powf(10000.f, -(float)i * (1.f / 16.f));
    float ang  = (float)t * freq;
    float c = cosf(ang), s = sinf(ang);
    const float* rowq = QK + (size_t)bt * 512 + h * 32;
    const float* rowk = rowq + 256;
    float g  = gain[h] * 0.17677669529663687f;
    float q1 = rowq[i], q2 = rowq[i + 16];
    float k1 = rowk[i], k2 = rowk[i + 16];
    float qa = (q1 * c - q2 * s) * g;
    float qb = (q2 * c + q1 * s) * g;
    float ka = (k1 * c - k2 * s);
    float kb = (k2 * c + k1 * s);
    size_t base = ((size_t)(b * HH + h) * TT + t) * DP;
    __nv_bfloat16 hh;
    hh = __float2bfloat16_rn(qa); Qh[base + i]      = hh; Ql[base + i]      = __float2bfloat16_rn(qa - __bfloat162float(hh));
    hh = __float2bfloat16_rn(qb); Qh[base + i + 16] = hh; Ql[base + i + 16] = __float2bfloat16_rn(qb - __bfloat162float(hh));
    hh = __float2bfloat16_rn(ka); Kh[base + i]      = hh; Kl[base + i]      = __float2bfloat16_rn(ka - __bfloat162float(hh));
    hh = __float2bfloat16_rn(kb); Kh[base + i + 16] = hh; Kl[base + i + 16] = __float2bfloat16_rn(kb - __bfloat162float(hh));
}

// ---------------- flash attention: pre-split bf16 + cp.async pipeline ----------------
#define FKP 40
#define FVP 72
#define SKH 0
#define SKL 2560
#define SVH 5120
#define SVL 9728
#define FSTG 14336

__global__ __launch_bounds__(256, 1)
void flash_mma(const __nv_bfloat16* __restrict__ Qh, const __nv_bfloat16* __restrict__ Ql,
               const __nv_bfloat16* __restrict__ Kh, const __nv_bfloat16* __restrict__ Kl,
               const __nv_bfloat16* __restrict__ Vh, const __nv_bfloat16* __restrict__ Vl,
               const float* __restrict__ V,
               __nv_bfloat16* __restrict__ Yh, __nv_bfloat16* __restrict__ Yl) {
    extern __shared__ __align__(16) __nv_bfloat16 fs[];
    uint32_t sb = smem_u32(fs);

    int b = blockIdx.z, h = blockIdx.y;
    int qt = (int)gridDim.x - 1 - (int)blockIdx.x;     // heavy blocks first
    int tid = threadIdx.x, lane = tid & 31, wid = tid >> 5;
    int gid = lane >> 2, tig = lane & 3;
    int qrow0 = qt * 128;

    size_t bh = (size_t)(b * HH + h) * TT;
    const __nv_bfloat16* Khg = Kh + bh * DP;
    const __nv_bfloat16* Klg = Kl + bh * DP;
    const __nv_bfloat16* Vhg = Vh + (size_t)b * TT * CC + h * DH;
    const __nv_bfloat16* Vlg = Vl + (size_t)b * TT * CC + h * DH;
    const float* Vb = V + (size_t)b * TT * CC + h * DH;

    // ---- stage Q into stage-0 smem, grab fragments ----
#pragma unroll
    for (int it = 0; it < 4; it++) {
        int c = it * 256 + tid;
        int row = (c & 511) >> 2, col = (c & 3) << 3;
        const __nv_bfloat16* src = (c < 512) ? (Qh + (bh + qrow0 + row) * DP + col)
                                             : (Ql + (bh + qrow0 + row) * DP + col);
        uint32_t doff = (c < 512) ? (uint32_t)(row * FKP + col) : (uint32_t)(5120 + row * FKP + col);
        *(uint4*)&fs[doff] = *(const uint4*)src;
    }
    __syncthreads();
    uint32_t qfh[2][4], qfl[2][4];
    {
        uint32_t arow = (uint32_t)(wid * 16 + (lane & 15)) * FKP + (uint32_t)((lane >> 4) << 3);
#pragma unroll
        for (int ks = 0; ks < 2; ks++) {
            ldsm4(qfh[ks], sb + 2 * (arow + ks * 16));
            ldsm4(qfl[ks], sb + 2 * (5120 + arow + ks * 16));
        }
    }
    __syncthreads();

    float m0 = -1e30f, m1 = -1e30f, l0 = 0.f, l1 = 0.f;
    float o[8][4];
#pragma unroll
    for (int nt = 0; nt < 8; nt++)
#pragma unroll
        for (int e = 0; e < 4; e++) o[nt][e] = 0.f;

    int wmax = qrow0 + wid * 16 + 15;
    int ntiles = 2 * qt + 2;

    auto issue = [&](int t, int s) {
        uint32_t st = sb + 2 * (uint32_t)(s * FSTG);
        int j0 = t * 64;
#pragma unroll
        for (int it = 0; it < 6; it++) {
            int c = it * 256 + tid;
            if (c < 512) {
                int row = (c & 255) >> 2, col = (c & 3) << 3;
                const __nv_bfloat16* src = (c < 256) ? (Khg + (size_t)(j0 + row) * DP + col)
                                                     : (Klg + (size_t)(j0 + row) * DP + col);
                uint32_t doff = (c < 256) ? (uint32_t)(SKH + row * FKP + col)
                                          : (uint32_t)(SKL + row * FKP + col);
                CP16(st + 2 * doff, src);
            } else {
                int cc = c - 512;
                int row = (cc & 511) >> 3, col = (cc & 7) << 3;
                const __nv_bfloat16* src = (cc < 512) ? (Vhg + (size_t)(j0 + row) * CC + col)
                                                      : (Vlg + (size_t)(j0 + row) * CC + col);
                uint32_t doff = (cc < 512) ? (uint32_t)(SVH + row * FVP + col)
                                           : (uint32_t)(SVL + row * FVP + col);
                CP16(st + 2 * doff, src);
            }
        }
    };

    issue(0, 0);
    CP_COMMIT();

    for (int t = 0; t < ntiles; t++) {
        int s = t & 1;
        if (t + 1 < ntiles) { issue(t + 1, s ^ 1); CP_COMMIT(); CP_WAIT1(); }
        else                { CP_WAIT0(); }
        __syncthreads();

        int j0 = t * 64;
        uint32_t stg = sb + 2 * (uint32_t)(s * FSTG);
        if (j0 <= wmax) {
            // ---- QK^T ----
            float sc[8][4];
#pragma unroll
            for (int nt = 0; nt < 8; nt++)
#pragma unroll
                for (int e = 0; e < 4; e++) sc[nt][e] = 0.f;
            uint32_t kbase = (uint32_t)(lane & 7) * FKP + (uint32_t)(((lane >> 3) & 3) << 3);
#pragma unroll
            for (int nt = 0; nt < 8; nt++) {
                uint32_t kbh[4], kbl[4];
                uint32_t ka = stg + 2 * (kbase + (uint32_t)(nt * 8) * FKP);
                ldsm4(kbh, ka + 2 * SKH);
                ldsm4(kbl, ka + 2 * SKL);
                mma16816(sc[nt], qfh[0], kbh);
                mma16816(sc[nt], qfh[1], kbh + 2);
                mma16816(sc[nt], qfh[0], kbl);
                mma16816(sc[nt], qfh[1], kbl + 2);
                mma16816(sc[nt], qfl[0], kbh);
                mma16816(sc[nt], qfl[1], kbh + 2);
            }
            // ---- causal mask ----
            if (j0 + 63 > qrow0 + wid * 16) {
                int r0 = qrow0 + wid * 16 + gid, r1 = r0 + 8;
#pragma unroll
                for (int nt = 0; nt < 8; nt++) {
                    int c = j0 + nt * 8 + tig * 2;
                    if (c > r0)     sc[nt][0] = -1e30f;
                    if (c + 1 > r0) sc[nt][1] = -1e30f;
                    if (c > r1)     sc[nt][2] = -1e30f;
                    if (c + 1 > r1) sc[nt][3] = -1e30f;
                }
            }
            // ---- online softmax ----
            float mx0 = -1e30f, mx1 = -1e30f;
#pragma unroll
            for (int nt = 0; nt < 8; nt++) {
                mx0 = fmaxf(mx0, fmaxf(sc[nt][0], sc[nt][1]));
                mx1 = fmaxf(mx1, fmaxf(sc[nt][2], sc[nt][3]));
            }
            mx0 = fmaxf(mx0, __shfl_xor_sync(~0u, mx0, 1));
            mx0 = fmaxf(mx0, __shfl_xor_sync(~0u, mx0, 2));
            mx1 = fmaxf(mx1, __shfl_xor_sync(~0u, mx1, 1));
            mx1 = fmaxf(mx1, __shfl_xor_sync(~0u, mx1, 2));
            float mn0 = fmaxf(m0, mx0), mn1 = fmaxf(m1, mx1);
            float cr0 = __expf(m0 - mn0), cr1 = __expf(m1 - mn1);
            m0 = mn0; m1 = mn1;
            float ls0 = 0.f, ls1 = 0.f;
#pragma unroll
            for (int nt = 0; nt < 8; nt++) {
                sc[nt][0] = __expf(sc[nt][0] - m0);
                sc[nt][1] = __expf(sc[nt][1] - m0);
                sc[nt][2] = __expf(sc[nt][2] - m1);
                sc[nt][3] = __expf(sc[nt][3] - m1);
                ls0 += sc[nt][0] + sc[nt][1];
                ls1 += sc[nt][2] + sc[nt][3];
            }
            l0 = l0 * cr0 + ls0;
            l1 = l1 * cr1 + ls1;
#pragma unroll
            for (int nt = 0; nt < 8; nt++) {
                o[nt][0] *= cr0; o[nt][1] *= cr0;
                o[nt][2] *= cr1; o[nt][3] *= cr1;
            }
            // ---- P @ V ----
            uint32_t vbase = (uint32_t)(lane & 15) * FVP + (uint32_t)((lane >> 4) << 3);
#pragma unroll
            for (int kk = 0; kk < 4; kk++) {
                uint32_t ah[4], al[4];
                split2(sc[2*kk][0],   sc[2*kk][1],   ah[0], al[0]);
                split2(sc[2*kk][2],   sc[2*kk][3],   ah[1], al[1]);
                split2(sc[2*kk+1][0], sc[2*kk+1][1], ah[2], al[2]);
                split2(sc[2*kk+1][2], sc[2*kk+1][3], ah[3], al[3]);
#pragma unroll
                for (int nv = 0; nv < 4; nv++) {
                    uint32_t vbh[4], vbl[4];
                    uint32_t va = stg + 2 * (vbase + (uint32_t)(kk * 16) * FVP + (uint32_t)(nv * 16));
                    ldsm4t(vbh, va + 2 * SVH);
                    ldsm4t(vbl, va + 2 * SVL);
                    mma16816(o[2*nv],     ah, vbh);
                    mma16816(o[2*nv + 1], ah, vbh + 2);
                    mma16816(o[2*nv],     ah, vbl);
                    mma16816(o[2*nv + 1], ah, vbl + 2);
                    mma16816(o[2*nv],     al, vbh);
                    mma16816(o[2*nv + 1], al, vbh + 2);
                }
            }
        }
        __syncthreads();
    }

    // ---- finalize: normalize, self-align, write bf16 hi/lo ----
    l0 += __shfl_xor_sync(~0u, l0, 1); l0 += __shfl_xor_sync(~0u, l0, 2);
    l1 += __shfl_xor_sync(~0u, l1, 1); l1 += __shfl_xor_sync(~0u, l1, 2);
    float inv0 = 1.f / l0, inv1 = 1.f / l1;
#pragma unroll
    for (int nt = 0; nt < 8; nt++) {
        o[nt][0] *= inv0; o[nt][1] *= inv0;
        o[nt][2] *= inv1; o[nt][3] *= inv1;
    }
    int i0 = qrow0 + wid * 16 + gid, i1 = i0 + 8;
    float dot0 = 0.f, n20 = 0.f, dot1 = 0.f, n21 = 0.f;
#pragma unroll
    for (int nt = 0; nt < 8; nt++) {
        int d = nt * 8 + tig * 2;
        float2 v0 = *(const float2*)&Vb[(size_t)i0 * CC + d];
        float2 v1 = *(const float2*)&Vb[(size_t)i1 * CC + d];
        dot0 += o[nt][0] * v0.x + o[nt][1] * v0.y;
        n20  += v0.x * v0.x + v0.y * v0.y;
        dot1 += o[nt][2] * v1.x + o[nt][3] * v1.y;
        n21  += v1.x * v1.x + v1.y * v1.y;
    }
    dot0 += __shfl_xor_sync(~0u, dot0, 1); dot0 += __shfl_xor_sync(~0u, dot0, 2);
    n20  += __shfl_xor_sync(~0u, n20, 1);  n20  += __shfl_xor_sync(~0u, n20, 2);
    dot1 += __shfl_xor_sync(~0u, dot1, 1); dot1 += __shfl_xor_sync(~0u, dot1, 2);
    n21  += __shfl_xor_sync(~0u, n21, 1);  n21  += __shfl_xor_sync(~0u, n21, 2);
    float nr0 = fmaxf(sqrtf(n20), 1e-12f);
    float nr1 = fmaxf(sqrtf(n21), 1e-12f);
    dot0 /= (nr0 * nr0);
    dot1 /= (nr1 * nr1);
    size_t o0 = (size_t)(b * TT + i0) * CC + h * DH;
    size_t o1 = (size_t)(b * TT + i1) * CC + h * DH;
#pragma unroll
    for (int nt = 0; nt < 8; nt++) {
        int d = nt * 8 + tig * 2;
        float2 v0 = *(const float2*)&Vb[(size_t)i0 * CC + d];
        float2 v1 = *(const float2*)&Vb[(size_t)i1 * CC + d];
        float y0x = o[nt][0] - dot0 * v0.x, y0y = o[nt][1] - dot0 * v0.y;
        float y1x = o[nt][2] - dot1 * v1.x, y1y = o[nt][3] - dot1 * v1.y;
        uint32_t hh, ll;
        split2(y0x, y0y, hh, ll);
        *(uint32_t*)&Yh[o0 + d] = hh; *(uint32_t*)&Yl[o0 + d] = ll;
        split2(y1x, y1y, hh, ll);
        *(uint32_t*)&Yh[o1 + d] = hh; *(uint32_t*)&Yl[o1 + d] = ll;
    }
}

// ---------------- layernorm (row of 512) -> bf16 hi/lo ----------------
__global__ void ln_kernel(const float* __restrict__ X, const float* __restrict__ g,
                          const float* __restrict__ bta,
                          __nv_bfloat16* __restrict__ Oh, __nv_bfloat16* __restrict__ Ol) {
    int row = blockIdx.x;
    int t = threadIdx.x;
    __shared__ float red[4], red2[4];
    const float* xp = X + (size_t)row * 512;
    float4 v = *(const float4*)&xp[t * 4];
    float s = v.x + v.y + v.z + v.w;
#pragma unroll
    for (int off = 16; off; off >>= 1) s += __shfl_xor_sync(~0u, s, off);
    if ((t & 31) == 0) red[t >> 5] = s;
    __syncthreads();
    float mean = (red[0] + red[1] + red[2] + red[3]) * (1.f / 512.f);
    float dx = v.x - mean, dy = v.y - mean, dz = v.z - mean, dw = v.w - mean;
    float s2 = dx*dx + dy*dy + dz*dz + dw*dw;
#pragma unroll
    for (int off = 16; off; off >>= 1) s2 += __shfl_xor_sync(~0u, s2, off);
    if ((t & 31) == 0) red2[t >> 5] = s2;
    __syncthreads();
    float var = (red2[0] + red2[1] + red2[2] + red2[3]) * (1.f / 512.f);
    float rsv = rsqrtf(var + 1e-5f);
    float4 gg = *(const float4*)&g[t * 4];
    float4 bb = *(const float4*)&bta[t * 4];
    float ox = dx * rsv * gg.x + bb.x;
    float oy = dy * rsv * gg.y + bb.y;
    float oz = dz * rsv * gg.z + bb.z;
    float ow = dw * rsv * gg.w + bb.w;
    uint2 h, l;
    split2(ox, oy, h.x, l.x); split2(oz, ow, h.y, l.y);
    *(uint2*)&Oh[(size_t)row * 512 + t * 4] = h;
    *(uint2*)&Ol[(size_t)row * 512 + t * 4] = l;
}

// ---------------- rms + out-proj (32) + tanh/temp ----------------
__global__ void final_kernel(const float* __restrict__ X, const float* __restrict__ Wout,
                             const float* __restrict__ ct, float* __restrict__ Z) {
    int row = blockIdx.x;
    int t = threadIdx.x;
    __shared__ __align__(16) float xs[512];
    __shared__ float red[8];
    __shared__ float pm[32][9];
    const float* xp = X + (size_t)row * 512;
    float2 v = *(const float2*)&xp[t * 2];
    float s2 = v.x * v.x + v.y * v.y;
#pragma unroll
    for (int off = 16; off; off >>= 1) s2 += __shfl_xor_sync(~0u, s2, off);
    if ((t & 31) == 0) red[t >> 5] = s2;
    __syncthreads();
    float tot = 0.f;
#pragma unroll
    for (int w = 0; w < 8; w++) tot += red[w];
    float rs = rsqrtf(tot * (1.f / 512.f) + 1e-6f);
    xs[t*2] = v.x * rs; xs[t*2+1] = v.y * rs;
    __syncthreads();
    int mi = t >> 3, seg = t & 7;
    const float* wrow = Wout + mi * 512 + seg * 64;
    const float* xseg = xs + seg * 64;
    float acc = 0.f;
#pragma unroll
    for (int d = 0; d < 64; d += 4) {
        float4 wv = *(const float4*)&wrow[d];
        acc += xseg[d]*wv.x + xseg[d+1]*wv.y + xseg[d+2]*wv.z + xseg[d+3]*wv.w;
    }
    pm[mi][seg] = acc;
    __syncthreads();
    if (t < 32) {
        float a = 0.f;
#pragma unroll
        for (int sgi = 0; sgi < 8; sgi++) a += pm[t][sgi];
        float cv = ct[t];
        float sp = (cv > 20.f) ? cv : log1pf(expf(cv));
        Z[(size_t)row * 32 + t] = tanhf(a / (sp + 1e-4f));
    }
}

// ---------------- launch ----------------
extern "C" void kernel_launch(void* const* d_in, const int* in_sizes, int n_in,
                              void* d_out, int out_size) {
    const float* x       = (const float*)d_in[0];
    const float* q_projs = (const float*)d_in[1];
    const float* k_projs = (const float*)d_in[2];
    const float* w_v     = (const float*)d_in[3];
    const float* w_proj  = (const float*)d_in[4];
    const float* q_gain  = (const float*)d_in[5];
    const float* enc_w0  = (const float*)d_in[6];
    const float* ln1g    = (const float*)d_in[7];
    const float* ln1b    = (const float*)d_in[8];
    const float* enc_w1  = (const float*)d_in[9];
    const float* ln2g    = (const float*)d_in[10];
    const float* ln2b    = (const float*)d_in[11];
    const float* enc_w2  = (const float*)d_in[12];
    const float* enc_wo  = (const float*)d_in[13];
    const float* ctemp   = (const float*)d_in[14];
    float* out = (float*)d_out;

    float *p_qk, *p_v, *p_h, *p_t0, *p_t1, *p_t2;
    __nv_bfloat16 *p_xh, *p_xl, *p_wqkh, *p_wqkl, *p_wvh, *p_wvl, *p_wph, *p_wpl;
    __nv_bfloat16 *p_w0h, *p_w0l, *p_w1h, *p_w1l, *p_w2h, *p_w2l;
    __nv_bfloat16 *p_qh, *p_ql, *p_kh, *p_kl, *p_vh, *p_vl;
    __nv_bfloat16 *p_yh, *p_yl, *p_hh, *p_hl, *p_lnh, *p_lnl;
    cudaGetSymbolAddress((void**)&p_qk,  g_qk);
    cudaGetSymbolAddress((void**)&p_v,   g_v);
    cudaGetSymbolAddress((void**)&p_h,   g_h);
    cudaGetSymbolAddress((void**)&p_t0,  g_t0);
    cudaGetSymbolAddress((void**)&p_t1,  g_t1);
    cudaGetSymbolAddress((void**)&p_t2,  g_t2);
    cudaGetSymbolAddress((void**)&p_xh,  g_xh);   cudaGetSymbolAddress((void**)&p_xl,  g_xl);
    cudaGetSymbolAddress((void**)&p_wqkh, g_wqkh); cudaGetSymbolAddress((void**)&p_wqkl, g_wqkl);
    cudaGetSymbolAddress((void**)&p_wvh, g_wvh);  cudaGetSymbolAddress((void**)&p_wvl, g_wvl);
    cudaGetSymbolAddress((void**)&p_wph, g_wph);  cudaGetSymbolAddress((void**)&p_wpl, g_wpl);
    cudaGetSymbolAddress((void**)&p_w0h, g_w0h);  cudaGetSymbolAddress((void**)&p_w0l, g_w0l);
    cudaGetSymbolAddress((void**)&p_w1h, g_w1h);  cudaGetSymbolAddress((void**)&p_w1l, g_w1l);
    cudaGetSymbolAddress((void**)&p_w2h, g_w2h);  cudaGetSymbolAddress((void**)&p_w2l, g_w2l);
    cudaGetSymbolAddress((void**)&p_qh,  g_qh);   cudaGetSymbolAddress((void**)&p_ql,  g_ql);
    cudaGetSymbolAddress((void**)&p_kh,  g_kh);   cudaGetSymbolAddress((void**)&p_kl,  g_kl);
    cudaGetSymbolAddress((void**)&p_vh,  g_vh);   cudaGetSymbolAddress((void**)&p_vl,  g_vl);
    cudaGetSymbolAddress((void**)&p_yh,  g_yh);   cudaGetSymbolAddress((void**)&p_yl,  g_yl);
    cudaGetSymbolAddress((void**)&p_hh,  g_hh);   cudaGetSymbolAddress((void**)&p_hl,  g_hl);
    cudaGetSymbolAddress((void**)&p_lnh, g_lnh);  cudaGetSymbolAddress((void**)&p_lnl, g_lnl);

    const int GEMM_SMEM  = 2 * GSTG * 2;   // 81920 B
    const int FLASH_SMEM = 2 * FSTG * 2;   // 57344 B
    cudaFuncSetAttribute(gemm_bf16, cudaFuncAttributeMaxDynamicSharedMemorySize, GEMM_SMEM);
    cudaFuncSetAttribute(flash_mma, cudaFuncAttributeMaxDynamicSharedMemorySize, FLASH_SMEM);

    dim3 ggrid(512 / 128, MM / 128);   // (4, 32)

    // pre-split inputs (once)
    split_kernel<<<MM*512/4/256, 256>>>(x, p_xh, p_xl, MM*512/4);
    split_kernel<<<256, 256>>>(w_v,    p_wvh, p_wvl, 65536);
    split_kernel<<<256, 256>>>(w_proj, p_wph, p_wpl, 65536);
    split_kernel<<<256, 256>>>(enc_w0, p_w0h, p_w0l, 65536);
    split_kernel<<<256, 256>>>(enc_w1, p_w1h, p_w1l, 65536);
    split_kernel<<<256, 256>>>(enc_w2, p_w2h, p_w2l, 65536);
    repack_kernel<<<512, 256>>>(q_projs, k_projs, p_wqkh, p_wqkl);

    gemm_bf16<<<ggrid, 256, GEMM_SMEM>>>(p_xh, p_xl, p_wqkh, p_wqkl, nullptr, p_qk, 0, nullptr, nullptr);
    rope_kernel<<<MM, 128>>>(p_qk, q_gain, p_qh, p_ql, p_kh, p_kl);
    gemm_bf16<<<ggrid, 256, GEMM_SMEM>>>(p_xh, p_xl, p_wvh, p_wvl, nullptr, p_v, 0, p_vh, p_vl);
    flash_mma<<<dim3(TT / 128, HH, BB), 256, FLASH_SMEM>>>(p_qh, p_ql, p_kh, p_kl,
                                                           p_vh, p_vl, p_v, p_yh, p_yl);
    gemm_bf16<<<ggrid, 256, GEMM_SMEM>>>(p_yh, p_yl, p_wph, p_wpl, x, p_h, 1, p_hh, p_hl);
    gemm_bf16<<<ggrid, 256, GEMM_SMEM>>>(p_hh, p_hl, p_w0h, p_w0l, nullptr, p_t0, 0, nullptr, nullptr);
    ln_kernel<<<MM, 128>>>(p_t0, ln1g, ln1b, p_lnh, p_lnl);
    gemm_bf16<<<ggrid, 256, GEMM_SMEM>>>(p_lnh, p_lnl, p_w1h, p_w1l, p_h, p_t1, 2, nullptr, nullptr);
    ln_kernel<<<MM, 128>>>(p_t1, ln2g, ln2b, p_lnh, p_lnl);
    gemm_bf16<<<ggrid, 256, GEMM_SMEM>>>(p_lnh, p_lnl, p_w2h, p_w2l, p_t1, p_t2, 2, nullptr, nullptr);
    final_kernel<<<MM, 256>>>(p_t2, enc_wo, ctemp, out);
}

// round 11
// speedup vs baseline: 1.0351x; 1.0278x over previous
#include <cuda_runtime.h>
#include <cuda_bf16.h>
#include <math.h>
#include <stdint.h>

// ---------------- problem constants ----------------
#define BB 2
#define TT 2048
#define CC 512
#define HH 8
#define DP 32
#define DH 64
#define MM (BB*TT)          // 4096 rows

// ---------------- scratch (no allocs allowed) ----------------
__device__ float g_qk [MM*512];
__device__ float g_v  [MM*CC];
__device__ float g_h  [MM*CC];
__device__ float g_t0 [MM*CC];
__device__ float g_t1 [MM*CC];
__device__ float g_t2 [MM*CC];
__device__ __nv_bfloat16 g_xh [MM*CC],  g_xl [MM*CC];
__device__ __nv_bfloat16 g_wbh[1024*512], g_wbl[1024*512];   // rows 0-511 wqk, 512-1023 wv
__device__ __nv_bfloat16 g_wph[512*512],  g_wpl[512*512];
__device__ __nv_bfloat16 g_w0h[512*512],  g_w0l[512*512];
__device__ __nv_bfloat16 g_w1h[512*512],  g_w1l[512*512];
__device__ __nv_bfloat16 g_w2h[512*512],  g_w2l[512*512];
__device__ __nv_bfloat16 g_qh[BB*HH*TT*DP], g_ql[BB*HH*TT*DP];
__device__ __nv_bfloat16 g_kh[BB*HH*TT*DP], g_kl[BB*HH*TT*DP];
__device__ __nv_bfloat16 g_vh[MM*CC], g_vl[MM*CC];
__device__ __nv_bfloat16 g_yh[MM*CC], g_yl[MM*CC];
__device__ __nv_bfloat16 g_hh[MM*CC], g_hl[MM*CC];
__device__ __nv_bfloat16 g_lnh[MM*CC], g_lnl[MM*CC];

// ---------------- helpers ----------------
__device__ __forceinline__ uint32_t smem_u32(const void* p) {
    uint32_t a;
    asm("{ .reg .u64 t; cvta.to.shared.u64 t, %1; cvt.u32.u64 %0, t; }" : "=r"(a) : "l"(p));
    return a;
}
__device__ __forceinline__ void ldsm4(uint32_t* r, uint32_t addr) {
    asm volatile("ldmatrix.sync.aligned.m8n8.x4.shared.b16 {%0,%1,%2,%3}, [%4];"
        : "=r"(r[0]), "=r"(r[1]), "=r"(r[2]), "=r"(r[3]) : "r"(addr));
}
__device__ __forceinline__ void ldsm4t(uint32_t* r, uint32_t addr) {
    asm volatile("ldmatrix.sync.aligned.m8n8.x4.trans.shared.b16 {%0,%1,%2,%3}, [%4];"
        : "=r"(r[0]), "=r"(r[1]), "=r"(r[2]), "=r"(r[3]) : "r"(addr));
}
__device__ __forceinline__ void ldsm2(uint32_t* r, uint32_t addr) {
    asm volatile("ldmatrix.sync.aligned.m8n8.x2.shared.b16 {%0,%1}, [%2];"
        : "=r"(r[0]), "=r"(r[1]) : "r"(addr));
}
__device__ __forceinline__ void mma16816(float* d, const uint32_t* a, const uint32_t* b) {
    asm volatile("mma.sync.aligned.m16n8k16.row.col.f32.bf16.bf16.f32 "
        "{%0,%1,%2,%3}, {%4,%5,%6,%7}, {%8,%9}, {%0,%1,%2,%3};"
        : "+f"(d[0]), "+f"(d[1]), "+f"(d[2]), "+f"(d[3])
        : "r"(a[0]), "r"(a[1]), "r"(a[2]), "r"(a[3]), "r"(b[0]), "r"(b[1]));
}
__device__ __forceinline__ void split2(float x, float y, uint32_t& hi, uint32_t& lo) {
    __nv_bfloat162 h = __floats2bfloat162_rn(x, y);
    float2 hf = __bfloat1622float2(h);
    __nv_bfloat162 l = __floats2bfloat162_rn(x - hf.x, y - hf.y);
    hi = *(uint32_t*)&h; lo = *(uint32_t*)&l;
}
#define CP16(dst, src) \
    asm volatile("cp.async.cg.shared.global [%0], [%1], 16;" :: "r"(dst), "l"(src))
#define CP_COMMIT() asm volatile("cp.async.commit_group;" ::: "memory")
#define CP_WAIT1()  asm volatile("cp.async.wait_group 1;" ::: "memory")
#define CP_WAIT0()  asm volatile("cp.async.wait_group 0;" ::: "memory")

// ---------------- splits ----------------
__global__ void splitx_kernel(const float* __restrict__ X,
                              __nv_bfloat16* __restrict__ H, __nv_bfloat16* __restrict__ L) {
    int i = blockIdx.x * 256 + threadIdx.x;          // 524288 float4s
    float4 v = ((const float4*)X)[i];
    uint2 h, l;
    split2(v.x, v.y, h.x, l.x); split2(v.z, v.w, h.y, l.y);
    ((uint2*)H)[i] = h; ((uint2*)L)[i] = l;
}

__global__ void split5_kernel(const float* __restrict__ s0, const float* __restrict__ s1,
                              const float* __restrict__ s2, const float* __restrict__ s3,
                              const float* __restrict__ s4,
                              __nv_bfloat16* h0, __nv_bfloat16* l0,
                              __nv_bfloat16* h1, __nv_bfloat16* l1,
                              __nv_bfloat16* h2, __nv_bfloat16* l2,
                              __nv_bfloat16* h3, __nv_bfloat16* l3,
                              __nv_bfloat16* h4, __nv_bfloat16* l4) {
    int i = blockIdx.x * 256 + threadIdx.x;          // 65536 float4s each
    const float* S; __nv_bfloat16 *H, *L;
    switch (blockIdx.y) {
        case 0: S = s0; H = h0; L = l0; break;
        case 1: S = s1; H = h1; L = l1; break;
        case 2: S = s2; H = h2; L = l2; break;
        case 3: S = s3; H = h3; L = l3; break;
        default: S = s4; H = h4; L = l4; break;
    }
    float4 v = ((const float4*)S)[i];
    uint2 h, l;
    split2(v.x, v.y, h.x, l.x); split2(v.z, v.w, h.y, l.y);
    ((uint2*)H)[i] = h; ((uint2*)L)[i] = l;
}

// ---------------- repack q/k projections + split to hi/lo ----------------
__global__ void repack_kernel(const float* __restrict__ qp, const float* __restrict__ kp,
                              __nv_bfloat16* __restrict__ Wh, __nv_bfloat16* __restrict__ Wl) {
    int idx = blockIdx.x * 256 + threadIdx.x;
    if (idx >= 256*512) return;
    int n = idx >> 9, d = idx & 511;
    int h = n >> 5, o = n & 31;
    float vq = qp[((h<<9)+d)*32 + o];
    float vk = kp[((h<<9)+d)*32 + o];
    __nv_bfloat16 hh;
    hh = __float2bfloat16_rn(vq);
    Wh[idx] = hh; Wl[idx] = __float2bfloat16_rn(vq - __bfloat162float(hh));
    hh = __float2bfloat16_rn(vk);
    Wh[(256<<9) + idx] = hh; Wl[(256<<9) + idx] = __float2bfloat16_rn(vk - __bfloat162float(hh));
}

// ---------------- pure-bf16 mma.sync GEMM: 128x128 tile, cp.async 2-stage ----------------
// mode 0: C=acc ; 1: C=acc+R ; 2: C=R+silu(acc) ; 3: QKV split (col<512 -> C, else C2 + hi/lo)
#define GPAD 40
#define OFF_AH 0
#define OFF_AL 5120
#define OFF_BH 10240
#define OFF_BL 15360
#define GSTG   20480          // bf16 elems per stage (40960 B)

template<int NB>
__global__ __launch_bounds__(256, NB)
void gemm_bf16(const __nv_bfloat16* __restrict__ Ah, const __nv_bfloat16* __restrict__ Al,
               const __nv_bfloat16* __restrict__ Bh, const __nv_bfloat16* __restrict__ Bl,
               const float* __restrict__ R, float* __restrict__ C, float* __restrict__ C2,
               int mode, __nv_bfloat16* __restrict__ Chi, __nv_bfloat16* __restrict__ Clo) {
    extern __shared__ __align__(16) __nv_bfloat16 s[];
    uint32_t sb0 = smem_u32(s);

    int tid = threadIdx.x;
    int lane = tid & 31, wid = tid >> 5;
    int wm = wid >> 2, wn = wid & 3;           // 2 x 4 warps (64 x 32 tiles)
    int row0 = blockIdx.y * 128, col0 = blockIdx.x * 128;

    float acc[4][4][4];
#pragma unroll
    for (int mi = 0; mi < 4; mi++)
#pragma unroll
        for (int ni = 0; ni < 4; ni++)
#pragma unroll
            for (int e = 0; e < 4; e++) acc[mi][ni][e] = 0.f;

    auto issue = [&](int k, int st) {
        uint32_t s0 = sb0 + 2 * (uint32_t)(st * GSTG);
        int kc = k * 32;
#pragma unroll
        for (int it = 0; it < 8; it++) {
            int mat = it >> 1;                       // 0=Ah 1=Al 2=Bh 3=Bl
            int cc  = ((it & 1) << 8) + tid;         // 0..511
            int r   = cc >> 2, col = (cc & 3) << 3;
            const __nv_bfloat16* g =
                (mat == 0) ? Ah + (size_t)(row0 + r) * 512 + kc + col :
                (mat == 1) ? Al + (size_t)(row0 + r) * 512 + kc + col :
                (mat == 2) ? Bh + (size_t)(col0 + r) * 512 + kc + col :
                             Bl + (size_t)(col0 + r) * 512 + kc + col;
            CP16(s0 + 2 * (uint32_t)(mat * 5120 + r * GPAD + col), g);
        }
    };

    issue(0, 0);
    CP_COMMIT();

    for (int k = 0; k < 16; k++) {
        int cur = k & 1;
        if (k < 15) { issue(k + 1, cur ^ 1); CP_COMMIT(); CP_WAIT1(); }
        else        { CP_WAIT0(); }
        __syncthreads();

        uint32_t sb = sb0 + (uint32_t)cur * (GSTG * 2);
        int l16 = lane & 15;
        uint32_t arow = (uint32_t)(wm * 64 + (lane & 15)) * GPAD + (uint32_t)((lane >> 4) << 3);
        uint32_t brow = (uint32_t)(wn * 32 + (l16 & 7)) * GPAD + (uint32_t)((l16 >> 3) << 3);
#pragma unroll
        for (int ks = 0; ks < 2; ks++) {
            uint32_t a[4][4], bh[4][2], bl[4][2];
#pragma unroll
            for (int mi = 0; mi < 4; mi++)
                ldsm4(a[mi], sb + 2 * (OFF_AH + arow + (uint32_t)(mi * 16) * GPAD + ks * 16));
#pragma unroll
            for (int ni = 0; ni < 4; ni++) {
                uint32_t ba = sb + 2 * (brow + (uint32_t)(ni * 8) * GPAD + ks * 16);
                ldsm2(bh[ni], ba + 2 * OFF_BH);
                ldsm2(bl[ni], ba + 2 * OFF_BL);
            }
#pragma unroll
            for (int mi = 0; mi < 4; mi++)
#pragma unroll
                for (int ni = 0; ni < 4; ni++) mma16816(acc[mi][ni], a[mi], bh[ni]);
#pragma unroll
            for (int mi = 0; mi < 4; mi++)
#pragma unroll
                for (int ni = 0; ni < 4; ni++) mma16816(acc[mi][ni], a[mi], bl[ni]);
#pragma unroll
            for (int mi = 0; mi < 4; mi++)
                ldsm4(a[mi], sb + 2 * (OFF_AL + arow + (uint32_t)(mi * 16) * GPAD + ks * 16));
#pragma unroll
            for (int mi = 0; mi < 4; mi++)
#pragma unroll
                for (int ni = 0; ni < 4; ni++) mma16816(acc[mi][ni], a[mi], bh[ni]);
        }
        __syncthreads();
    }

    int gid = lane >> 2, tig = lane & 3;
#pragma unroll
    for (int mi = 0; mi < 4; mi++) {
#pragma unroll
        for (int ni = 0; ni < 4; ni++) {
            int rg = row0 + wm * 64 + mi * 16 + gid;
            int cg = col0 + wn * 32 + ni * 8 + tig * 2;
#pragma unroll
            for (int half = 0; half < 2; half++) {
                int r = rg + half * 8;
                float vx = acc[mi][ni][half * 2], vy = acc[mi][ni][half * 2 + 1];
                if (mode == 3) {
                    if (col0 < 512) {
                        size_t gi = (size_t)r * 512 + cg;
                        float2 ov; ov.x = vx; ov.y = vy;
                        *(float2*)&C[gi] = ov;
                    } else {
                        size_t gi = (size_t)r * 512 + (cg - 512);
                        float2 ov; ov.x = vx; ov.y = vy;
                        *(float2*)&C2[gi] = ov;
                        uint32_t hh, ll;
                        split2(vx, vy, hh, ll);
                        *(uint32_t*)&Chi[gi] = hh;
                        *(uint32_t*)&Clo[gi] = ll;
                    }
                } else {
                    size_t gi = (size_t)r * 512 + cg;
                    if (mode == 1) {
                        float2 rv = *(const float2*)&R[gi];
                        vx += rv.x; vy += rv.y;
                    } else if (mode == 2) {
                        float2 rv = *(const float2*)&R[gi];
                        vx = rv.x + vx / (1.f + __expf(-vx));
                        vy = rv.y + vy / (1.f + __expf(-vy));
                    }
                    float2 ov; ov.x = vx; ov.y = vy;
                    *(float2*)&C[gi] = ov;
                    if (Chi) {
                        uint32_t hh, ll;
                        split2(vx, vy, hh, ll);
                        *(uint32_t*)&Chi[gi] = hh;
                        *(uint32_t*)&Clo[gi] = ll;
                    }
                }
            }
        }
    }
}

// ---------------- RoPE + gain (+ scale folded into q), bf16 hi/lo outputs ----------------
__global__ void rope_kernel(const float* __restrict__ QK, const float* __restrict__ gain,
                            __nv_bfloat16* __restrict__ Qh, __nv_bfloat16* __restrict__ Ql,
                            __nv_bfloat16* __restrict__ Kh, __nv_bfloat16* __restrict__ Kl) {
    int bt = blockIdx.x;
    int t  = bt & (TT - 1);
    int b  = bt >> 11;
    int tid = threadIdx.x;
    int h = tid >> 4, i = tid & 15;
    float freq = powf(10000.f, -(float)i * (1.f / 16.f));
    float ang  = (float)t * freq;
    float c = cosf(ang), s = sinf(ang);
    const float* rowq = QK + (size_t)bt * 512 + h * 32;
    const float* rowk = rowq + 256;
    float g  = gain[h] * 0.17677669529663687f;
    float q1 = rowq[i], q2 = rowq[i + 16];
    float k1 = rowk[i], k2 = rowk[i + 16];
    float qa = (q1 * c - q2 * s) * g;
    float qb = (q2 * c + q1 * s) * g;
    float ka = (k1 * c - k2 * s);
    float kb = (k2 * c + k1 * s);
    size_t base = ((size_t)(b * HH + h) * TT + t) * DP;
    __nv_bfloat16 hh;
    hh = __float2bfloat16_rn(qa); Qh[base + i]      = hh; Ql[base + i]      = __float2bfloat16_rn(qa - __bfloat162float(hh));
    hh = __float2bfloat16_rn(qb); Qh[base + i + 16] = hh; Ql[base + i + 16] = __float2bfloat16_rn(qb - __bfloat162float(hh));
    hh = __float2bfloat16_rn(ka); Kh[base + i]      = hh; Kl[base + i]      = __float2bfloat16_rn(ka - __bfloat162float(hh));
    hh = __float2bfloat16_rn(kb); Kh[base + i + 16] = hh; Kl[base + i + 16] = __float2bfloat16_rn(kb - __bfloat162float(hh));
}

// ---------------- flash attention: pre-split bf16 + cp.async pipeline ----------------
#define FKP 40
#define FVP 72
#define SKH 0
#define SKL 2560
#define SVH 5120
#define SVL 9728
#define FSTG 14336

__global__ __launch_bounds__(256, 1)
void flash_mma(const __nv_bfloat16* __restrict__ Qh, const __nv_bfloat16* __restrict__ Ql,
               const __nv_bfloat16* __restrict__ Kh, const __nv_bfloat16* __restrict__ Kl,
               const __nv_bfloat16* __restrict__ Vh, const __nv_bfloat16* __restrict__ Vl,
               const float* __restrict__ V,
               __nv_bfloat16* __restrict__ Yh, __nv_bfloat16* __restrict__ Yl) {
    extern __shared__ __align__(16) __nv_bfloat16 fs[];
    uint32_t sb = smem_u32(fs);

    int b = blockIdx.z, h = blockIdx.y;
    int qt = (int)gridDim.x - 1 - (int)blockIdx.x;     // heavy blocks first
    int tid = threadIdx.x, lane = tid & 31, wid = tid >> 5;
    int gid = lane >> 2, tig = lane & 3;
    int qrow0 = qt * 128;

    size_t bh = (size_t)(b * HH + h) * TT;
    const __nv_bfloat16* Khg = Kh + bh * DP;
    const __nv_bfloat16* Klg = Kl + bh * DP;
    const __nv_bfloat16* Vhg = Vh + (size_t)b * TT * CC + h * DH;
    const __nv_bfloat16* Vlg = Vl + (size_t)b * TT * CC + h * DH;
    const float* Vb = V + (size_t)b * TT * CC + h * DH;

    // ---- stage Q into stage-0 smem, grab fragments ----
#pragma unroll
    for (int it = 0; it < 4; it++) {
        int c = it * 256 + tid;
        int row = (c & 511) >> 2, col = (c & 3) << 3;
        const __nv_bfloat16* src = (c < 512) ? (Qh + (bh + qrow0 + row) * DP + col)
                                             : (Ql + (bh + qrow0 + row) * DP + col);
        uint32_t doff = (c < 512) ? (uint32_t)(row * FKP + col) : (uint32_t)(5120 + row * FKP + col);
        *(uint4*)&fs[doff] = *(const uint4*)src;
    }
    __syncthreads();
    uint32_t qfh[2][4], qfl[2][4];
    {
        uint32_t arow = (uint32_t)(wid * 16 + (lane & 15)) * FKP + (uint32_t)((lane >> 4) << 3);
#pragma unroll
        for (int ks = 0; ks < 2; ks++) {
            ldsm4(qfh[ks], sb + 2 * (arow + ks * 16));
            ldsm4(qfl[ks], sb + 2 * (5120 + arow + ks * 16));
        }
    }
    __syncthreads();

    float m0 = -1e30f, m1 = -1e30f, l0 = 0.f, l1 = 0.f;
    float o[8][4];
#pragma unroll
    for (int nt = 0; nt < 8; nt++)
#pragma unroll
        for (int e = 0; e < 4; e++) o[nt][e] = 0.f;

    int wmax = qrow0 + wid * 16 + 15;
    int ntiles = 2 * qt + 2;

    auto issue = [&](int t, int s) {
        uint32_t st = sb + 2 * (uint32_t)(s * FSTG);
        int j0 = t * 64;
#pragma unroll
        for (int it = 0; it < 6; it++) {
            int c = it * 256 + tid;
            if (c < 512) {
                int row = (c & 255) >> 2, col = (c & 3) << 3;
                const __nv_bfloat16* src = (c < 256) ? (Khg + (size_t)(j0 + row) * DP + col)
                                                     : (Klg + (size_t)(j0 + row) * DP + col);
                uint32_t doff = (c < 256) ? (uint32_t)(SKH + row * FKP + col)
                                          : (uint32_t)(SKL + row * FKP + col);
                CP16(st + 2 * doff, src);
            } else {
                int cc = c - 512;
                int row = (cc & 511) >> 3, col = (cc & 7) << 3;
                const __nv_bfloat16* src = (cc < 512) ? (Vhg + (size_t)(j0 + row) * CC + col)
                                                      : (Vlg + (size_t)(j0 + row) * CC + col);
                uint32_t doff = (cc < 512) ? (uint32_t)(SVH + row * FVP + col)
                                           : (uint32_t)(SVL + row * FVP + col);
                CP16(st + 2 * doff, src);
            }
        }
    };

    issue(0, 0);
    CP_COMMIT();

    for (int t = 0; t < ntiles; t++) {
        int s = t & 1;
        if (t + 1 < ntiles) { issue(t + 1, s ^ 1); CP_COMMIT(); CP_WAIT1(); }
        else                { CP_WAIT0(); }
        __syncthreads();

        int j0 = t * 64;
        uint32_t stg = sb + 2 * (uint32_t)(s * FSTG);
        if (j0 <= wmax) {
            float sc[8][4];
#pragma unroll
            for (int nt = 0; nt < 8; nt++)
#pragma unroll
                for (int e = 0; e < 4; e++) sc[nt][e] = 0.f;
            uint32_t kbase = (uint32_t)(lane & 7) * FKP + (uint32_t)(((lane >> 3) & 3) << 3);
#pragma unroll
            for (int nt = 0; nt < 8; nt++) {
                uint32_t kbh[4], kbl[4];
                uint32_t ka = stg + 2 * (kbase + (uint32_t)(nt * 8) * FKP);
                ldsm4(kbh, ka + 2 * SKH);
                ldsm4(kbl, ka + 2 * SKL);
                mma16816(sc[nt], qfh[0], kbh);
                mma16816(sc[nt], qfh[1], kbh + 2);
                mma16816(sc[nt], qfh[0], kbl);
                mma16816(sc[nt], qfh[1], kbl + 2);
                mma16816(sc[nt], qfl[0], kbh);
                mma16816(sc[nt], qfl[1], kbh + 2);
            }
            if (j0 + 63 > qrow0 + wid * 16) {
                int r0 = qrow0 + wid * 16 + gid, r1 = r0 + 8;
#pragma unroll
                for (int nt = 0; nt < 8; nt++) {
                    int c = j0 + nt * 8 + tig * 2;
                    if (c > r0)     sc[nt][0] = -1e30f;
                    if (c + 1 > r0) sc[nt][1] = -1e30f;
                    if (c > r1)     sc[nt][2] = -1e30f;
                    if (c + 1 > r1) sc[nt][3] = -1e30f;
                }
            }
            float mx0 = -1e30f, mx1 = -1e30f;
#pragma unroll
            for (int nt = 0; nt < 8; nt++) {
                mx0 = fmaxf(mx0, fmaxf(sc[nt][0], sc[nt][1]));
                mx1 = fmaxf(mx1, fmaxf(sc[nt][2], sc[nt][3]));
            }
            mx0 = fmaxf(mx0, __shfl_xor_sync(~0u, mx0, 1));
            mx0 = fmaxf(mx0, __shfl_xor_sync(~0u, mx0, 2));
            mx1 = fmaxf(mx1, __shfl_xor_sync(~0u, mx1, 1));
            mx1 = fmaxf(mx1, __shfl_xor_sync(~0u, mx1, 2));
            float mn0 = fmaxf(m0, mx0), mn1 = fmaxf(m1, mx1);
            float cr0 = __expf(m0 - mn0), cr1 = __expf(m1 - mn1);
            m0 = mn0; m1 = mn1;
            float ls0 = 0.f, ls1 = 0.f;
#pragma unroll
            for (int nt = 0; nt < 8; nt++) {
                sc[nt][0] = __expf(sc[nt][0] - m0);
                sc[nt][1] = __expf(sc[nt][1] - m0);
                sc[nt][2] = __expf(sc[nt][2] - m1);
                sc[nt][3] = __expf(sc[nt][3] - m1);
                ls0 += sc[nt][0] + sc[nt][1];
                ls1 += sc[nt][2] + sc[nt][3];
            }
            l0 = l0 * cr0 + ls0;
            l1 = l1 * cr1 + ls1;
#pragma unroll
            for (int nt = 0; nt < 8; nt++) {
                o[nt][0] *= cr0; o[nt][1] *= cr0;
                o[nt][2] *= cr1; o[nt][3] *= cr1;
            }
            uint32_t vbase = (uint32_t)(lane & 15) * FVP + (uint32_t)((lane >> 4) << 3);
#pragma unroll
            for (int kk = 0; kk < 4; kk++) {
                uint32_t ah[4], al[4];
                split2(sc[2*kk][0],   sc[2*kk][1],   ah[0], al[0]);
                split2(sc[2*kk][2],   sc[2*kk][3],   ah[1], al[1]);
                split2(sc[2*kk+1][0], sc[2*kk+1][1], ah[2], al[2]);
                split2(sc[2*kk+1][2], sc[2*kk+1][3], ah[3], al[3]);
#pragma unroll
                for (int nv = 0; nv < 4; nv++) {
                    uint32_t vbh[4], vbl[4];
                    uint32_t va = stg + 2 * (vbase + (uint32_t)(kk * 16) * FVP + (uint32_t)(nv * 16));
                    ldsm4t(vbh, va + 2 * SVH);
                    ldsm4t(vbl, va + 2 * SVL);
                    mma16816(o[2*nv],     ah, vbh);
                    mma16816(o[2*nv + 1], ah, vbh + 2);
                    mma16816(o[2*nv],     ah, vbl);
                    mma16816(o[2*nv + 1], ah, vbl + 2);
                    mma16816(o[2*nv],     al, vbh);
                    mma16816(o[2*nv + 1], al, vbh + 2);
                }
            }
        }
        __syncthreads();
    }

    l0 += __shfl_xor_sync(~0u, l0, 1); l0 += __shfl_xor_sync(~0u, l0, 2);
    l1 += __shfl_xor_sync(~0u, l1, 1); l1 += __shfl_xor_sync(~0u, l1, 2);
    float inv0 = 1.f / l0, inv1 = 1.f / l1;
#pragma unroll
    for (int nt = 0; nt < 8; nt++) {
        o[nt][0] *= inv0; o[nt][1] *= inv0;
        o[nt][2] *= inv1; o[nt][3] *= inv1;
    }
    int i0 = qrow0 + wid * 16 + gid, i1 = i0 + 8;
    float dot0 = 0.f, n20 = 0.f, dot1 = 0.f, n21 = 0.f;
#pragma unroll
    for (int nt = 0; nt < 8; nt++) {
        int d = nt * 8 + tig * 2;
        float2 v0 = *(const float2*)&Vb[(size_t)i0 * CC + d];
        float2 v1 = *(const float2*)&Vb[(size_t)i1 * CC + d];
        dot0 += o[nt][0] * v0.x + o[nt][1] * v0.y;
        n20  += v0.x * v0.x + v0.y * v0.y;
        dot1 += o[nt][2] * v1.x + o[nt][3] * v1.y;
        n21  += v1.x * v1.x + v1.y * v1.y;
    }
    dot0 += __shfl_xor_sync(~0u, dot0, 1); dot0 += __shfl_xor_sync(~0u, dot0, 2);
    n20  += __shfl_xor_sync(~0u, n20, 1);  n20  += __shfl_xor_sync(~0u, n20, 2);
    dot1 += __shfl_xor_sync(~0u, dot1, 1); dot1 += __shfl_xor_sync(~0u, dot1, 2);
    n21  += __shfl_xor_sync(~0u, n21, 1);  n21  += __shfl_xor_sync(~0u, n21, 2);
    float nr0 = fmaxf(sqrtf(n20), 1e-12f);
    float nr1 = fmaxf(sqrtf(n21), 1e-12f);
    dot0 /= (nr0 * nr0);
    dot1 /= (nr1 * nr1);
    size_t o0 = (size_t)(b * TT + i0) * CC + h * DH;
    size_t o1 = (size_t)(b * TT + i1) * CC + h * DH;
#pragma unroll
    for (int nt = 0; nt < 8; nt++) {
        int d = nt * 8 + tig * 2;
        float2 v0 = *(const float2*)&Vb[(size_t)i0 * CC + d];
        float2 v1 = *(const float2*)&Vb[(size_t)i1 * CC + d];
        float y0x = o[nt][0] - dot0 * v0.x, y0y = o[nt][1] - dot0 * v0.y;
        float y1x = o[nt][2] - dot1 * v1.x, y1y = o[nt][3] - dot1 * v1.y;
        uint32_t hh, ll;
        split2(y0x, y0y, hh, ll);
        *(uint32_t*)&Yh[o0 + d] = hh; *(uint32_t*)&Yl[o0 + d] = ll;
        split2(y1x, y1y, hh, ll);
        *(uint32_t*)&Yh[o1 + d] = hh; *(uint32_t*)&Yl[o1 + d] = ll;
    }
}

// ---------------- layernorm (row of 512) -> bf16 hi/lo ----------------
__global__ void ln_kernel(const float* __restrict__ X, const float* __restrict__ g,
                          const float* __restrict__ bta,
                          __nv_bfloat16* __restrict__ Oh, __nv_bfloat16* __restrict__ Ol) {
    int row = blockIdx.x;
    int t = threadIdx.x;
    __shared__ float red[4], red2[4];
    const float* xp = X + (size_t)row * 512;
    float4 v = *(const float4*)&xp[t * 4];
    float s = v.x + v.y + v.z + v.w;
#pragma unroll
    for (int off = 16; off; off >>= 1) s += __shfl_xor_sync(~0u, s, off);
    if ((t & 31) == 0) red[t >> 5] = s;
    __syncthreads();
    float mean = (red[0] + red[1] + red[2] + red[3]) * (1.f / 512.f);
    float dx = v.x - mean, dy = v.y - mean, dz = v.z - mean, dw = v.w - mean;
    float s2 = dx*dx + dy*dy + dz*dz + dw*dw;
#pragma unroll
    for (int off = 16; off; off >>= 1) s2 += __shfl_xor_sync(~0u, s2, off);
    if ((t & 31) == 0) red2[t >> 5] = s2;
    __syncthreads();
    float var = (red2[0] + red2[1] + red2[2] + red2[3]) * (1.f / 512.f);
    float rsv = rsqrtf(var + 1e-5f);
    float4 gg = *(const float4*)&g[t * 4];
    float4 bb = *(const float4*)&bta[t * 4];
    float ox = dx * rsv * gg.x + bb.x;
    float oy = dy * rsv * gg.y + bb.y;
    float oz = dz * rsv * gg.z + bb.z;
    float ow = dw * rsv * gg.w + bb.w;
    uint2 h, l;
    split2(ox, oy, h.x, l.x); split2(oz, ow, h.y, l.y);
    *(uint2*)&Oh[(size_t)row * 512 + t * 4] = h;
    *(uint2*)&Ol[(size_t)row * 512 + t * 4] = l;
}

// ---------------- rms + out-proj (32) + tanh/temp ----------------
__global__ void final_kernel(const float* __restrict__ X, const float* __restrict__ Wout,
                             const float* __restrict__ ct, float* __restrict__ Z) {
    int row = blockIdx.x;
    int t = threadIdx.x;
    __shared__ __align__(16) float xs[512];
    __shared__ float red[8];
    __shared__ float pm[32][9];
    const float* xp = X + (size_t)row * 512;
    float2 v = *(const float2*)&xp[t * 2];
    float s2 = v.x * v.x + v.y * v.y;
#pragma unroll
    for (int off = 16; off; off >>= 1) s2 += __shfl_xor_sync(~0u, s2, off);
    if ((t & 31) == 0) red[t >> 5] = s2;
    __syncthreads();
    float tot = 0.f;
#pragma unroll
    for (int w = 0; w < 8; w++) tot += red[w];
    float rs = rsqrtf(tot * (1.f / 512.f) + 1e-6f);
    xs[t*2] = v.x * rs; xs[t*2+1] = v.y * rs;
    __syncthreads();
    int mi = t >> 3, seg = t & 7;
    const float* wrow = Wout + mi * 512 + seg * 64;
    const float* xseg = xs + seg * 64;
    float acc = 0.f;
#pragma unroll
    for (int d = 0; d < 64; d += 4) {
        float4 wv = *(const float4*)&wrow[d];
        acc += xseg[d]*wv.x + xseg[d+1]*wv.y + xseg[d+2]*wv.z + xseg[d+3]*wv.w;
    }
    pm[mi][seg] = acc;
    __syncthreads();
    if (t < 32) {
        float a = 0.f;
#pragma unroll
        for (int sgi = 0; sgi < 8; sgi++) a += pm[t][sgi];
        float cv = ct[t];
        float sp = (cv > 20.f) ? cv : log1pf(expf(cv));
        Z[(size_t)row * 32 + t] = tanhf(a / (sp + 1e-4f));
    }
}

// ---------------- launch ----------------
extern "C" void kernel_launch(void* const* d_in, const int* in_sizes, int n_in,
                              void* d_out, int out_size) {
    const float* x       = (const float*)d_in[0];
    const float* q_projs = (const float*)d_in[1];
    const float* k_projs = (const float*)d_in[2];
    const float* w_v     = (const float*)d_in[3];
    const float* w_proj  = (const float*)d_in[4];
    const float* q_gain  = (const float*)d_in[5];
    const float* enc_w0  = (const float*)d_in[6];
    const float* ln1g    = (const float*)d_in[7];
    const float* ln1b    = (const float*)d_in[8];
    const float* enc_w1  = (const float*)d_in[9];
    const float* ln2g    = (const float*)d_in[10];
    const float* ln2b    = (const float*)d_in[11];
    const float* enc_w2  = (const float*)d_in[12];
    const float* enc_wo  = (const float*)d_in[13];
    const float* ctemp   = (const float*)d_in[14];
    float* out = (float*)d_out;

    float *p_qk, *p_v, *p_h, *p_t0, *p_t1, *p_t2;
    __nv_bfloat16 *p_xh, *p_xl, *p_wbh, *p_wbl, *p_wph, *p_wpl;
    __nv_bfloat16 *p_w0h, *p_w0l, *p_w1h, *p_w1l, *p_w2h, *p_w2l;
    __nv_bfloat16 *p_qh, *p_ql, *p_kh, *p_kl, *p_vh, *p_vl;
    __nv_bfloat16 *p_yh, *p_yl, *p_hh, *p_hl, *p_lnh, *p_lnl;
    cudaGetSymbolAddress((void**)&p_qk,  g_qk);
    cudaGetSymbolAddress((void**)&p_v,   g_v);
    cudaGetSymbolAddress((void**)&p_h,   g_h);
    cudaGetSymbolAddress((void**)&p_t0,  g_t0);
    cudaGetSymbolAddress((void**)&p_t1,  g_t1);
    cudaGetSymbolAddress((void**)&p_t2,  g_t2);
    cudaGetSymbolAddress((void**)&p_xh,  g_xh);   cudaGetSymbolAddress((void**)&p_xl,  g_xl);
    cudaGetSymbolAddress((void**)&p_wbh, g_wbh);  cudaGetSymbolAddress((void**)&p_wbl, g_wbl);
    cudaGetSymbolAddress((void**)&p_wph, g_wph);  cudaGetSymbolAddress((void**)&p_wpl, g_wpl);
    cudaGetSymbolAddress((void**)&p_w0h, g_w0h);  cudaGetSymbolAddress((void**)&p_w0l, g_w0l);
    cudaGetSymbolAddress((void**)&p_w1h, g_w1h);  cudaGetSymbolAddress((void**)&p_w1l, g_w1l);
    cudaGetSymbolAddress((void**)&p_w2h, g_w2h);  cudaGetSymbolAddress((void**)&p_w2l, g_w2l);
    cudaGetSymbolAddress((void**)&p_qh,  g_qh);   cudaGetSymbolAddress((void**)&p_ql,  g_ql);
    cudaGetSymbolAddress((void**)&p_kh,  g_kh);   cudaGetSymbolAddress((void**)&p_kl,  g_kl);
    cudaGetSymbolAddress((void**)&p_vh,  g_vh);   cudaGetSymbolAddress((void**)&p_vl,  g_vl);
    cudaGetSymbolAddress((void**)&p_yh,  g_yh);   cudaGetSymbolAddress((void**)&p_yl,  g_yl);
    cudaGetSymbolAddress((void**)&p_hh,  g_hh);   cudaGetSymbolAddress((void**)&p_hl,  g_hl);
    cudaGetSymbolAddress((void**)&p_lnh, g_lnh);  cudaGetSymbolAddress((void**)&p_lnl, g_lnl);

    const int GEMM_SMEM  = 2 * GSTG * 2;   // 81920 B
    const int FLASH_SMEM = 2 * FSTG * 2;   // 57344 B
    cudaFuncSetAttribute(gemm_bf16<1>, cudaFuncAttributeMaxDynamicSharedMemorySize, GEMM_SMEM);
    cudaFuncSetAttribute(gemm_bf16<2>, cudaFuncAttributeMaxDynamicSharedMemorySize, GEMM_SMEM);
    cudaFuncSetAttribute(flash_mma,    cudaFuncAttributeMaxDynamicSharedMemorySize, FLASH_SMEM);

    dim3 ggrid(4, 32);     // N=512 gemms
    dim3 gqkv(8, 32);      // merged N=1024

    // pre-splits (3 launches)
    splitx_kernel<<<2048, 256>>>(x, p_xh, p_xl);
    split5_kernel<<<dim3(256, 5), 256>>>(w_v, w_proj, enc_w0, enc_w1, enc_w2,
                                         p_wbh + 512*512, p_wbl + 512*512,
                                         p_wph, p_wpl, p_w0h, p_w0l,
                                         p_w1h, p_w1l, p_w2h, p_w2l);
    repack_kernel<<<512, 256>>>(q_projs, k_projs, p_wbh, p_wbl);

    // merged QK+V projection (N=1024, occ-2)
    gemm_bf16<2><<<gqkv, 256, GEMM_SMEM>>>(p_xh, p_xl, p_wbh, p_wbl,
                                           nullptr, p_qk, p_v, 3, p_vh, p_vl);
    rope_kernel<<<MM, 128>>>(p_qk, q_gain, p_qh, p_ql, p_kh, p_kl);
    flash_mma<<<dim3(TT / 128, HH, BB), 256, FLASH_SMEM>>>(p_qh, p_ql, p_kh, p_kl,
                                                           p_vh, p_vl, p_v, p_yh, p_yl);
    gemm_bf16<1><<<ggrid, 256, GEMM_SMEM>>>(p_yh, p_yl, p_wph, p_wpl, x, p_h, nullptr, 1, p_hh, p_hl);
    gemm_bf16<1><<<ggrid, 256, GEMM_SMEM>>>(p_hh, p_hl, p_w0h, p_w0l, nullptr, p_t0, nullptr, 0, nullptr, nullptr);
    ln_kernel<<<MM, 128>>>(p_t0, ln1g, ln1b, p_lnh, p_lnl);
    gemm_bf16<1><<<ggrid, 256, GEMM_SMEM>>>(p_lnh, p_lnl, p_w1h, p_w1l, p_h, p_t1, nullptr, 2, nullptr, nullptr);
    ln_kernel<<<MM, 128>>>(p_t1, ln2g, ln2b, p_lnh, p_lnl);
    gemm_bf16<1><<<ggrid, 256, GEMM_SMEM>>>(p_lnh, p_lnl, p_w2h, p_w2l, p_t1, p_t2, nullptr, 2, nullptr, nullptr);
    final_kernel<<<MM, 256>>>(p_t2, enc_wo, ctemp, out);
}

// round 12
// speedup vs baseline: 1.1248x; 1.0866x over previous
#include <cuda_runtime.h>
#include <cuda_bf16.h>
#include <cuda_fp16.h>
#include <math.h>
#include <stdint.h>

// ---------------- problem constants ----------------
#define BB 2
#define TT 2048
#define CC 512
#define HH 8
#define DP 32
#define DH 64
#define MM (BB*TT)          // 4096 rows

// ---------------- scratch (no allocs allowed) ----------------
__device__ float g_wqk[512*512];
__device__ float g_qk [MM*512];
__device__ float g_v  [MM*CC];
__device__ float g_h  [MM*CC];
__device__ float g_t0 [MM*CC];
__device__ float g_ln [MM*CC];
__device__ float g_t1 [MM*CC];
__device__ float g_t2 [MM*CC];
__device__ float g_y  [MM*CC];
__device__ __half g_qh[BB*HH*TT*DP], g_ql[BB*HH*TT*DP];
__device__ __half g_kh[BB*HH*TT*DP], g_kl[BB*HH*TT*DP];
__device__ __half g_vh[MM*CC], g_vl[MM*CC];

// ---------------- helpers ----------------
__device__ __forceinline__ uint32_t smem_u32(const void* p) {
    uint32_t a;
    asm("{ .reg .u64 t; cvta.to.shared.u64 t, %1; cvt.u32.u64 %0, t; }" : "=r"(a) : "l"(p));
    return a;
}
__device__ __forceinline__ void ldsm4(uint32_t* r, uint32_t addr) {
    asm volatile("ldmatrix.sync.aligned.m8n8.x4.shared.b16 {%0,%1,%2,%3}, [%4];"
        : "=r"(r[0]), "=r"(r[1]), "=r"(r[2]), "=r"(r[3]) : "r"(addr));
}
__device__ __forceinline__ void ldsm4t(uint32_t* r, uint32_t addr) {
    asm volatile("ldmatrix.sync.aligned.m8n8.x4.trans.shared.b16 {%0,%1,%2,%3}, [%4];"
        : "=r"(r[0]), "=r"(r[1]), "=r"(r[2]), "=r"(r[3]) : "r"(addr));
}
__device__ __forceinline__ void ldsm2(uint32_t* r, uint32_t addr) {
    asm volatile("ldmatrix.sync.aligned.m8n8.x2.shared.b16 {%0,%1}, [%2];"
        : "=r"(r[0]), "=r"(r[1]) : "r"(addr));
}
__device__ __forceinline__ void mma16816(float* d, const uint32_t* a, const uint32_t* b) {
    asm volatile("mma.sync.aligned.m16n8k16.row.col.f32.bf16.bf16.f32 "
        "{%0,%1,%2,%3}, {%4,%5,%6,%7}, {%8,%9}, {%0,%1,%2,%3};"
        : "+f"(d[0]), "+f"(d[1]), "+f"(d[2]), "+f"(d[3])
        : "r"(a[0]), "r"(a[1]), "r"(a[2]), "r"(a[3]), "r"(b[0]), "r"(b[1]));
}
__device__ __forceinline__ void mma16816h(float* d, const uint32_t* a, const uint32_t* b) {
    asm volatile("mma.sync.aligned.m16n8k16.row.col.f32.f16.f16.f32 "
        "{%0,%1,%2,%3}, {%4,%5,%6,%7}, {%8,%9}, {%0,%1,%2,%3};"
        : "+f"(d[0]), "+f"(d[1]), "+f"(d[2]), "+f"(d[3])
        : "r"(a[0]), "r"(a[1]), "r"(a[2]), "r"(a[3]), "r"(b[0]), "r"(b[1]));
}
__device__ __forceinline__ void split2(float x, float y, uint32_t& hi, uint32_t& lo) {
    __nv_bfloat162 h = __floats2bfloat162_rn(x, y);
    float2 hf = __bfloat1622float2(h);
    __nv_bfloat162 l = __floats2bfloat162_rn(x - hf.x, y - hf.y);
    hi = *(uint32_t*)&h; lo = *(uint32_t*)&l;
}
__device__ __forceinline__ void split2h(float x, float y, uint32_t& hi, uint32_t& lo) {
    __half2 h = __floats2half2_rn(x, y);
    float2 hf = __half22float2(h);
    __half2 l = __floats2half2_rn(x - hf.x, y - hf.y);
    hi = *(uint32_t*)&h; lo = *(uint32_t*)&l;
}
#define CP16(dst, src) \
    asm volatile("cp.async.cg.shared.global [%0], [%1], 16;" :: "r"(dst), "l"(src))
#define CP_COMMIT() asm volatile("cp.async.commit_group;" ::: "memory")
#define CP_WAIT1()  asm volatile("cp.async.wait_group 1;" ::: "memory")
#define CP_WAIT0()  asm volatile("cp.async.wait_group 0;" ::: "memory")

// ---------------- repack q/k projections into NT weight layout ----------------
__global__ void repack_kernel(const float* __restrict__ qp, const float* __restrict__ kp,
                              float* __restrict__ W) {
    int idx = blockIdx.x * 256 + threadIdx.x;
    if (idx >= 256*512) return;
    int n = idx >> 9, d = idx & 511;
    int h = n >> 5, o = n & 31;
    W[idx]            = qp[((h<<9)+d)*32 + o];
    W[(256<<9) + idx] = kp[((h<<9)+d)*32 + o];
}

// ---------------- bf16x3 mma.sync GEMM (R8 proven config) ----------------
#define GPAD 40
#define OFF_AH 0
#define OFF_AL 5120
#define OFF_BH 10240
#define OFF_BL 15360
#define GSTG   20480

__global__ __launch_bounds__(256, 1)
void gemm_mma(const float* __restrict__ A, const float* __restrict__ W,
              const float* __restrict__ R, float* __restrict__ C, int mode,
              __half* __restrict__ Chi, __half* __restrict__ Clo) {
    extern __shared__ __align__(16) char gsm[];
    __nv_bfloat16* s = (__nv_bfloat16*)gsm;
    uint32_t sb0 = smem_u32(s);

    int tid = threadIdx.x;
    int lane = tid & 31, wid = tid >> 5;
    int wm = wid >> 2, wn = wid & 3;
    int row0 = blockIdx.y * 128, col0 = blockIdx.x * 128;

    float acc[4][4][4];
#pragma unroll
    for (int mi = 0; mi < 4; mi++)
#pragma unroll
        for (int ni = 0; ni < 4; ni++)
#pragma unroll
            for (int e = 0; e < 4; e++) acc[mi][ni][e] = 0.f;

    float4 la[4], lb[4];
    int lrow[4], lc4[4];
#pragma unroll
    for (int it = 0; it < 4; it++) {
        int slot = it * 256 + tid;
        lrow[it] = slot >> 3;
        lc4[it]  = (slot & 7) << 2;
    }

#pragma unroll
    for (int it = 0; it < 4; it++) {
        la[it] = *(const float4*)&A[(size_t)(row0 + lrow[it]) * 512 + lc4[it]];
        lb[it] = *(const float4*)&W[(size_t)(col0 + lrow[it]) * 512 + lc4[it]];
    }
#pragma unroll
    for (int it = 0; it < 4; it++) {
        int base = lrow[it] * GPAD + lc4[it];
        uint2 h, l;
        split2(la[it].x, la[it].y, h.x, l.x); split2(la[it].z, la[it].w, h.y, l.y);
        *(uint2*)&s[OFF_AH + base] = h; *(uint2*)&s[OFF_AL + base] = l;
        split2(lb[it].x, lb[it].y, h.x, l.x); split2(lb[it].z, lb[it].w, h.y, l.y);
        *(uint2*)&s[OFF_BH + base] = h; *(uint2*)&s[OFF_BL + base] = l;
    }
    __syncthreads();

    for (int k = 0; k < 16; k++) {
        int cur = k & 1;
        if (k < 15) {
            int kc = (k + 1) * 32;
#pragma unroll
            for (int it = 0; it < 4; it++) {
                la[it] = *(const float4*)&A[(size_t)(row0 + lrow[it]) * 512 + kc + lc4[it]];
                lb[it] = *(const float4*)&W[(size_t)(col0 + lrow[it]) * 512 + kc + lc4[it]];
            }
        }
        uint32_t sb = sb0 + (uint32_t)cur * (GSTG * 2);
        int l16 = lane & 15;
        uint32_t arow = (uint32_t)(wm * 64 + (lane & 15)) * GPAD + (uint32_t)((lane >> 4) << 3);
        uint32_t brow = (uint32_t)(wn * 32 + (l16 & 7)) * GPAD + (uint32_t)((l16 >> 3) << 3);
#pragma unroll
        for (int ks = 0; ks < 2; ks++) {
            uint32_t a[4][4], bh[4][2], bl[4][2];
#pragma unroll
            for (int mi = 0; mi < 4; mi++)
                ldsm4(a[mi], sb + 2 * (OFF_AH + arow + (uint32_t)(mi * 16) * GPAD + ks * 16));
#pragma unroll
            for (int ni = 0; ni < 4; ni++) {
                uint32_t ba = sb + 2 * (brow + (uint32_t)(ni * 8) * GPAD + ks * 16);
                ldsm2(bh[ni], ba + 2 * OFF_BH);
                ldsm2(bl[ni], ba + 2 * OFF_BL);
            }
#pragma unroll
            for (int mi = 0; mi < 4; mi++)
#pragma unroll
                for (int ni = 0; ni < 4; ni++) mma16816(acc[mi][ni], a[mi], bh[ni]);
#pragma unroll
            for (int mi = 0; mi < 4; mi++)
#pragma unroll
                for (int ni = 0; ni < 4; ni++) mma16816(acc[mi][ni], a[mi], bl[ni]);
#pragma unroll
            for (int mi = 0; mi < 4; mi++)
                ldsm4(a[mi], sb + 2 * (OFF_AL + arow + (uint32_t)(mi * 16) * GPAD + ks * 16));
#pragma unroll
            for (int mi = 0; mi < 4; mi++)
#pragma unroll
                for (int ni = 0; ni < 4; ni++) mma16816(acc[mi][ni], a[mi], bh[ni]);
        }
        if (k < 15) {
            __nv_bfloat16* sn = s + (size_t)((k + 1) & 1) * GSTG;
#pragma unroll
            for (int it = 0; it < 4; it++) {
                int base = lrow[it] * GPAD + lc4[it];
                uint2 h, l;
                split2(la[it].x, la[it].y, h.x, l.x); split2(la[it].z, la[it].w, h.y, l.y);
                *(uint2*)&sn[OFF_AH + base] = h; *(uint2*)&sn[OFF_AL + base] = l;
                split2(lb[it].x, lb[it].y, h.x, l.x); split2(lb[it].z, lb[it].w, h.y, l.y);
                *(uint2*)&sn[OFF_BH + base] = h; *(uint2*)&sn[OFF_BL + base] = l;
            }
        }
        __syncthreads();
    }

    int gid = lane >> 2, tig = lane & 3;
#pragma unroll
    for (int mi = 0; mi < 4; mi++) {
#pragma unroll
        for (int ni = 0; ni < 4; ni++) {
            int rg = row0 + wm * 64 + mi * 16 + gid;
            int cg = col0 + wn * 32 + ni * 8 + tig * 2;
#pragma unroll
            for (int half = 0; half < 2; half++) {
                int r = rg + half * 8;
                float vx = acc[mi][ni][half * 2], vy = acc[mi][ni][half * 2 + 1];
                size_t gi = (size_t)r * 512 + cg;
                if (mode == 1) {
                    float2 rv = *(const float2*)&R[gi];
                    vx += rv.x; vy += rv.y;
                } else if (mode == 2) {
                    float2 rv = *(const float2*)&R[gi];
                    vx = rv.x + vx / (1.f + __expf(-vx));
                    vy = rv.y + vy / (1.f + __expf(-vy));
                }
                float2 ov; ov.x = vx; ov.y = vy;
                *(float2*)&C[gi] = ov;
                if (Chi) {
                    uint32_t hh, ll;
                    split2h(vx, vy, hh, ll);
                    *(uint32_t*)&Chi[gi] = hh;
                    *(uint32_t*)&Clo[gi] = ll;
                }
            }
        }
    }
}

// ---------------- RoPE + gain (+ scale folded into q), f16 hi/lo outputs ----------------
__global__ void rope_kernel(const float* __restrict__ QK, const float* __restrict__ gain,
                            __half* __restrict__ Qh, __half* __restrict__ Ql,
                            __half* __restrict__ Kh, __half* __restrict__ Kl) {
    int bt = blockIdx.x;
    int t  = bt & (TT - 1);
    int b  = bt >> 11;
    int tid = threadIdx.x;
    int h = tid >> 4, i = tid & 15;
    float freq = powf(10000.f, -(float)i * (1.f / 16.f));
    float ang  = (float)t * freq;
    float c = cosf(ang), s = sinf(ang);
    const float* rowq = QK + (size_t)bt * 512 + h * 32;
    const float* rowk = rowq + 256;
    float g  = gain[h] * 0.17677669529663687f;
    float q1 = rowq[i], q2 = rowq[i + 16];
    float k1 = rowk[i], k2 = rowk[i + 16];
    float qa = (q1 * c - q2 * s) * g;
    float qb = (q2 * c + q1 * s) * g;
    float ka = (k1 * c - k2 * s);
    float kb = (k2 * c + k1 * s);
    size_t base = ((size_t)(b * HH + h) * TT + t) * DP;
    __half hh;
    hh = __float2half_rn(qa); Qh[base + i]      = hh; Ql[base + i]      = __float2half_rn(qa - __half2float(hh));
    hh = __float2half_rn(qb); Qh[base + i + 16] = hh; Ql[base + i + 16] = __float2half_rn(qb - __half2float(hh));
    hh = __float2half_rn(ka); Kh[base + i]      = hh; Kl[base + i]      = __float2half_rn(ka - __half2float(hh));
    hh = __float2half_rn(kb); Kh[base + i + 16] = hh; Kl[base + i + 16] = __float2half_rn(kb - __half2float(hh));
}

// ---------------- flash attention: f16 pipeline, h2exp2 softmax ----------------
#define FKP 40
#define FVP 72
#define SKH 0
#define SKL 2560
#define SVH 5120
#define SVL 9728
#define FSTG 14336
#define L2E 1.4426950408889634f

__global__ __launch_bounds__(256, 1)
void flash_mma(const __half* __restrict__ Qh, const __half* __restrict__ Ql,
               const __half* __restrict__ Kh, const __half* __restrict__ Kl,
               const __half* __restrict__ Vh, const __half* __restrict__ Vl,
               const float* __restrict__ V, float* __restrict__ Y) {
    extern __shared__ __align__(16) __half fs[];
    uint32_t sb = smem_u32(fs);

    int b = blockIdx.z, h = blockIdx.y;
    int qt = (int)gridDim.x - 1 - (int)blockIdx.x;     // heavy blocks first
    int tid = threadIdx.x, lane = tid & 31, wid = tid >> 5;
    int gid = lane >> 2, tig = lane & 3;
    int qrow0 = qt * 128;

    size_t bh = (size_t)(b * HH + h) * TT;
    const __half* Khg = Kh + bh * DP;
    const __half* Klg = Kl + bh * DP;
    const __half* Vhg = Vh + (size_t)b * TT * CC + h * DH;
    const __half* Vlg = Vl + (size_t)b * TT * CC + h * DH;
    const float* Vb = V + (size_t)b * TT * CC + h * DH;

    // ---- stage Q into stage-0 smem, grab fragments ----
#pragma unroll
    for (int it = 0; it < 4; it++) {
        int c = it * 256 + tid;
        int row = (c & 511) >> 2, col = (c & 3) << 3;
        const __half* src = (c < 512) ? (Qh + (bh + qrow0 + row) * DP + col)
                                      : (Ql + (bh + qrow0 + row) * DP + col);
        uint32_t doff = (c < 512) ? (uint32_t)(row * FKP + col) : (uint32_t)(5120 + row * FKP + col);
        *(uint4*)&fs[doff] = *(const uint4*)src;
    }
    __syncthreads();
    uint32_t qfh[2][4], qfl[2][4];
    {
        uint32_t arow = (uint32_t)(wid * 16 + (lane & 15)) * FKP + (uint32_t)((lane >> 4) << 3);
#pragma unroll
        for (int ks = 0; ks < 2; ks++) {
            ldsm4(qfh[ks], sb + 2 * (arow + ks * 16));
            ldsm4(qfl[ks], sb + 2 * (5120 + arow + ks * 16));
        }
    }
    __syncthreads();

    float m0 = -1e30f, m1 = -1e30f, l0 = 0.f, l1 = 0.f;
    float o[8][4];
#pragma unroll
    for (int nt = 0; nt < 8; nt++)
#pragma unroll
        for (int e = 0; e < 4; e++) o[nt][e] = 0.f;

    int wmax = qrow0 + wid * 16 + 15;
    int ntiles = 2 * qt + 2;

    auto issue = [&](int t, int s) {
        uint32_t st = sb + 2 * (uint32_t)(s * FSTG);
        int j0 = t * 64;
#pragma unroll
        for (int it = 0; it < 6; it++) {
            int c = it * 256 + tid;
            if (c < 512) {
                int row = (c & 255) >> 2, col = (c & 3) << 3;
                const __half* src = (c < 256) ? (Khg + (size_t)(j0 + row) * DP + col)
                                              : (Klg + (size_t)(j0 + row) * DP + col);
                uint32_t doff = (c < 256) ? (uint32_t)(SKH + row * FKP + col)
                                          : (uint32_t)(SKL + row * FKP + col);
                CP16(st + 2 * doff, src);
            } else {
                int cc = c - 512;
                int row = (cc & 511) >> 3, col = (cc & 7) << 3;
                const __half* src = (cc < 512) ? (Vhg + (size_t)(j0 + row) * CC + col)
                                               : (Vlg + (size_t)(j0 + row) * CC + col);
                uint32_t doff = (cc < 512) ? (uint32_t)(SVH + row * FVP + col)
                                           : (uint32_t)(SVL + row * FVP + col);
                CP16(st + 2 * doff, src);
            }
        }
    };

    issue(0, 0);
    CP_COMMIT();

    for (int t = 0; t < ntiles; t++) {
        int s = t & 1;
        if (t + 1 < ntiles) { issue(t + 1, s ^ 1); CP_COMMIT(); CP_WAIT1(); }
        else                { CP_WAIT0(); }
        __syncthreads();

        int j0 = t * 64;
        uint32_t stg = sb + 2 * (uint32_t)(s * FSTG);
        if (j0 <= wmax) {
            // ---- QK^T (f16 hi/lo, 3 terms) ----
            float sc[8][4];
#pragma unroll
            for (int nt = 0; nt < 8; nt++)
#pragma unroll
                for (int e = 0; e < 4; e++) sc[nt][e] = 0.f;
            uint32_t kbase = (uint32_t)(lane & 7) * FKP + (uint32_t)(((lane >> 3) & 3) << 3);
#pragma unroll
            for (int nt = 0; nt < 8; nt++) {
                uint32_t kbh[4], kbl[4];
                uint32_t ka = stg + 2 * (kbase + (uint32_t)(nt * 8) * FKP);
                ldsm4(kbh, ka + 2 * SKH);
                ldsm4(kbl, ka + 2 * SKL);
                mma16816h(sc[nt], qfh[0], kbh);
                mma16816h(sc[nt], qfh[1], kbh + 2);
                mma16816h(sc[nt], qfh[0], kbl);
                mma16816h(sc[nt], qfh[1], kbl + 2);
                mma16816h(sc[nt], qfl[0], kbh);
                mma16816h(sc[nt], qfl[1], kbh + 2);
            }
            // ---- causal mask ----
            if (j0 + 63 > qrow0 + wid * 16) {
                int r0 = qrow0 + wid * 16 + gid, r1 = r0 + 8;
#pragma unroll
                for (int nt = 0; nt < 8; nt++) {
                    int c = j0 + nt * 8 + tig * 2;
                    if (c > r0)     sc[nt][0] = -1e30f;
                    if (c + 1 > r0) sc[nt][1] = -1e30f;
                    if (c > r1)     sc[nt][2] = -1e30f;
                    if (c + 1 > r1) sc[nt][3] = -1e30f;
                }
            }
            // ---- online softmax (f16x2 exp2) ----
            float mx0 = -1e30f, mx1 = -1e30f;
#pragma unroll
            for (int nt = 0; nt < 8; nt++) {
                mx0 = fmaxf(mx0, fmaxf(sc[nt][0], sc[nt][1]));
                mx1 = fmaxf(mx1, fmaxf(sc[nt][2], sc[nt][3]));
            }
            mx0 = fmaxf(mx0, __shfl_xor_sync(~0u, mx0, 1));
            mx0 = fmaxf(mx0, __shfl_xor_sync(~0u, mx0, 2));
            mx1 = fmaxf(mx1, __shfl_xor_sync(~0u, mx1, 1));
            mx1 = fmaxf(mx1, __shfl_xor_sync(~0u, mx1, 2));
            float mn0 = fmaxf(m0, mx0), mn1 = fmaxf(m1, mx1);
            float cr0 = __expf(m0 - mn0), cr1 = __expf(m1 - mn1);
            m0 = mn0; m1 = mn1;
            uint32_t pa[8], pb[8];
            float ls0 = 0.f, ls1 = 0.f;
#pragma unroll
            for (int nt = 0; nt < 8; nt++) {
                __half2 e0 = h2exp2(__floats2half2_rn((sc[nt][0] - m0) * L2E,
                                                      (sc[nt][1] - m0) * L2E));
                __half2 e1 = h2exp2(__floats2half2_rn((sc[nt][2] - m1) * L2E,
                                                      (sc[nt][3] - m1) * L2E));
                pa[nt] = *(uint32_t*)&e0;
                pb[nt] = *(uint32_t*)&e1;
                float2 f0 = __half22float2(e0);
                float2 f1 = __half22float2(e1);
                ls0 += f0.x + f0.y;
                ls1 += f1.x + f1.y;
            }
            l0 = l0 * cr0 + ls0;
            l1 = l1 * cr1 + ls1;
#pragma unroll
            for (int nt = 0; nt < 8; nt++) {
                o[nt][0] *= cr0; o[nt][1] *= cr0;
                o[nt][2] *= cr1; o[nt][3] *= cr1;
            }
            // ---- P @ V (f16 p x f16 V hi/lo, 2 terms) ----
            uint32_t vbase = (uint32_t)(lane & 15) * FVP + (uint32_t)((lane >> 4) << 3);
#pragma unroll
            for (int kk = 0; kk < 4; kk++) {
                uint32_t af[4];
                af[0] = pa[2*kk];     af[1] = pb[2*kk];
                af[2] = pa[2*kk + 1]; af[3] = pb[2*kk + 1];
#pragma unroll
                for (int nv = 0; nv < 4; nv++) {
                    uint32_t vbh[4], vbl[4];
                    uint32_t va = stg + 2 * (vbase + (uint32_t)(kk * 16) * FVP + (uint32_t)(nv * 16));
                    ldsm4t(vbh, va + 2 * SVH);
                    ldsm4t(vbl, va + 2 * SVL);
                    mma16816h(o[2*nv],     af, vbh);
                    mma16816h(o[2*nv + 1], af, vbh + 2);
                    mma16816h(o[2*nv],     af, vbl);
                    mma16816h(o[2*nv + 1], af, vbl + 2);
                }
            }
        }
        __syncthreads();
    }

    // ---- finalize ----
    l0 += __shfl_xor_sync(~0u, l0, 1); l0 += __shfl_xor_sync(~0u, l0, 2);
    l1 += __shfl_xor_sync(~0u, l1, 1); l1 += __shfl_xor_sync(~0u, l1, 2);
    float inv0 = 1.f / l0, inv1 = 1.f / l1;
#pragma unroll
    for (int nt = 0; nt < 8; nt++) {
        o[nt][0] *= inv0; o[nt][1] *= inv0;
        o[nt][2] *= inv1; o[nt][3] *= inv1;
    }
    int i0 = qrow0 + wid * 16 + gid, i1 = i0 + 8;
    float dot0 = 0.f, n20 = 0.f, dot1 = 0.f, n21 = 0.f;
#pragma unroll
    for (int nt = 0; nt < 8; nt++) {
        int d = nt * 8 + tig * 2;
        float2 v0 = *(const float2*)&Vb[(size_t)i0 * CC + d];
        float2 v1 = *(const float2*)&Vb[(size_t)i1 * CC + d];
        dot0 += o[nt][0] * v0.x + o[nt][1] * v0.y;
        n20  += v0.x * v0.x + v0.y * v0.y;
        dot1 += o[nt][2] * v1.x + o[nt][3] * v1.y;
        n21  += v1.x * v1.x + v1.y * v1.y;
    }
    dot0 += __shfl_xor_sync(~0u, dot0, 1); dot0 += __shfl_xor_sync(~0u, dot0, 2);
    n20  += __shfl_xor_sync(~0u, n20, 1);  n20  += __shfl_xor_sync(~0u, n20, 2);
    dot1 += __shfl_xor_sync(~0u, dot1, 1); dot1 += __shfl_xor_sync(~0u, dot1, 2);
    n21  += __shfl_xor_sync(~0u, n21, 1);  n21  += __shfl_xor_sync(~0u, n21, 2);
    float nr0 = fmaxf(sqrtf(n20), 1e-12f);
    float nr1 = fmaxf(sqrtf(n21), 1e-12f);
    dot0 /= (nr0 * nr0);
    dot1 /= (nr1 * nr1);
    float* Y0 = Y + (size_t)(b * TT + i0) * CC + h * DH;
    float* Y1 = Y + (size_t)(b * TT + i1) * CC + h * DH;
#pragma unroll
    for (int nt = 0; nt < 8; nt++) {
        int d = nt * 8 + tig * 2;
        float2 v0 = *(const float2*)&Vb[(size_t)i0 * CC + d];
        float2 v1 = *(const float2*)&Vb[(size_t)i1 * CC + d];
        float2 y0, y1;
        y0.x = o[nt][0] - dot0 * v0.x; y0.y = o[nt][1] - dot0 * v0.y;
        y1.x = o[nt][2] - dot1 * v1.x; y1.y = o[nt][3] - dot1 * v1.y;
        *(float2*)&Y0[d] = y0;
        *(float2*)&Y1[d] = y1;
    }
}

// ---------------- layernorm (row of 512) ----------------
__global__ void ln_kernel(const float* __restrict__ X, const float* __restrict__ g,
                          const float* __restrict__ bta, float* __restrict__ O) {
    int row = blockIdx.x;
    int t = threadIdx.x;
    __shared__ float red[4], red2[4];
    const float* xp = X + (size_t)row * 512;
    float4 v = *(const float4*)&xp[t * 4];
    float s = v.x + v.y + v.z + v.w;
#pragma unroll
    for (int off = 16; off; off >>= 1) s += __shfl_xor_sync(~0u, s, off);
    if ((t & 31) == 0) red[t >> 5] = s;
    __syncthreads();
    float mean = (red[0] + red[1] + red[2] + red[3]) * (1.f / 512.f);
    float dx = v.x - mean, dy = v.y - mean, dz = v.z - mean, dw = v.w - mean;
    float s2 = dx*dx + dy*dy + dz*dz + dw*dw;
#pragma unroll
    for (int off = 16; off; off >>= 1) s2 += __shfl_xor_sync(~0u, s2, off);
    if ((t & 31) == 0) red2[t >> 5] = s2;
    __syncthreads();
    float var = (red2[0] + red2[1] + red2[2] + red2[3]) * (1.f / 512.f);
    float rsv = rsqrtf(var + 1e-5f);
    float4 gg = *(const float4*)&g[t * 4];
    float4 bb = *(const float4*)&bta[t * 4];
    float4 ov;
    ov.x = dx * rsv * gg.x + bb.x;
    ov.y = dy * rsv * gg.y + bb.y;
    ov.z = dz * rsv * gg.z + bb.z;
    ov.w = dw * rsv * gg.w + bb.w;
    *(float4*)&O[(size_t)row * 512 + t * 4] = ov;
}

// ---------------- rms + out-proj (32) + tanh/temp ----------------
__global__ void final_kernel(const float* __restrict__ X, const float* __restrict__ Wout,
                             const float* __restrict__ ct, float* __restrict__ Z) {
    int row = blockIdx.x;
    int t = threadIdx.x;
    __shared__ __align__(16) float xs[512];
    __shared__ float red[8];
    __shared__ float pm[32][9];
    const float* xp = X + (size_t)row * 512;
    float2 v = *(const float2*)&xp[t * 2];
    float s2 = v.x * v.x + v.y * v.y;
#pragma unroll
    for (int off = 16; off; off >>= 1) s2 += __shfl_xor_sync(~0u, s2, off);
    if ((t & 31) == 0) red[t >> 5] = s2;
    __syncthreads();
    float tot = 0.f;
#pragma unroll
    for (int w = 0; w < 8; w++) tot += red[w];
    float rs = rsqrtf(tot * (1.f / 512.f) + 1e-6f);
    xs[t*2] = v.x * rs; xs[t*2+1] = v.y * rs;
    __syncthreads();
    int mi = t >> 3, seg = t & 7;
    const float* wrow = Wout + mi * 512 + seg * 64;
    const float* xseg = xs + seg * 64;
    float acc = 0.f;
#pragma unroll
    for (int d = 0; d < 64; d += 4) {
        float4 wv = *(const float4*)&wrow[d];
        acc += xseg[d]*wv.x + xseg[d+1]*wv.y + xseg[d+2]*wv.z + xseg[d+3]*wv.w;
    }
    pm[mi][seg] = acc;
    __syncthreads();
    if (t < 32) {
        float a = 0.f;
#pragma unroll
        for (int sgi = 0; sgi < 8; sgi++) a += pm[t][sgi];
        float cv = ct[t];
        float sp = (cv > 20.f) ? cv : log1pf(expf(cv));
        Z[(size_t)row * 32 + t] = tanhf(a / (sp + 1e-4f));
    }
}

// ---------------- launch ----------------
extern "C" void kernel_launch(void* const* d_in, const int* in_sizes, int n_in,
                              void* d_out, int out_size) {
    const float* x       = (const float*)d_in[0];
    const float* q_projs = (const float*)d_in[1];
    const float* k_projs = (const float*)d_in[2];
    const float* w_v     = (const float*)d_in[3];
    const float* w_proj  = (const float*)d_in[4];
    const float* q_gain  = (const float*)d_in[5];
    const float* enc_w0  = (const float*)d_in[6];
    const float* ln1g    = (const float*)d_in[7];
    const float* ln1b    = (const float*)d_in[8];
    const float* enc_w1  = (const float*)d_in[9];
    const float* ln2g    = (const float*)d_in[10];
    const float* ln2b    = (const float*)d_in[11];
    const float* enc_w2  = (const float*)d_in[12];
    const float* enc_wo  = (const float*)d_in[13];
    const float* ctemp   = (const float*)d_in[14];
    float* out = (float*)d_out;

    float *p_wqk, *p_qk, *p_v, *p_y, *p_h, *p_t0, *p_ln, *p_t1, *p_t2;
    __half *p_qh, *p_ql, *p_kh, *p_kl, *p_vh, *p_vl;
    cudaGetSymbolAddress((void**)&p_wqk, g_wqk);
    cudaGetSymbolAddress((void**)&p_qk,  g_qk);
    cudaGetSymbolAddress((void**)&p_v,   g_v);
    cudaGetSymbolAddress((void**)&p_y,   g_y);
    cudaGetSymbolAddress((void**)&p_h,   g_h);
    cudaGetSymbolAddress((void**)&p_t0,  g_t0);
    cudaGetSymbolAddress((void**)&p_ln,  g_ln);
    cudaGetSymbolAddress((void**)&p_t1,  g_t1);
    cudaGetSymbolAddress((void**)&p_t2,  g_t2);
    cudaGetSymbolAddress((void**)&p_qh,  g_qh);
    cudaGetSymbolAddress((void**)&p_ql,  g_ql);
    cudaGetSymbolAddress((void**)&p_kh,  g_kh);
    cudaGetSymbolAddress((void**)&p_kl,  g_kl);
    cudaGetSymbolAddress((void**)&p_vh,  g_vh);
    cudaGetSymbolAddress((void**)&p_vl,  g_vl);

    const int GEMM_SMEM  = 2 * GSTG * 2;   // 81920 B
    const int FLASH_SMEM = 2 * FSTG * 2;   // 57344 B
    cudaFuncSetAttribute(gemm_mma,  cudaFuncAttributeMaxDynamicSharedMemorySize, GEMM_SMEM);
    cudaFuncSetAttribute(flash_mma, cudaFuncAttributeMaxDynamicSharedMemorySize, FLASH_SMEM);

    dim3 ggrid(512 / 128, MM / 128);   // (4, 32)

    repack_kernel<<<512, 256>>>(q_projs, k_projs, p_wqk);
    gemm_mma<<<ggrid, 256, GEMM_SMEM>>>(x, p_wqk, nullptr, p_qk, 0, nullptr, nullptr);
    rope_kernel<<<MM, 128>>>(p_qk, q_gain, p_qh, p_ql, p_kh, p_kl);
    gemm_mma<<<ggrid, 256, GEMM_SMEM>>>(x, w_v, nullptr, p_v, 0, p_vh, p_vl);
    flash_mma<<<dim3(TT / 128, HH, BB), 256, FLASH_SMEM>>>(p_qh, p_ql, p_kh, p_kl,
                                                           p_vh, p_vl, p_v, p_y);
    gemm_mma<<<ggrid, 256, GEMM_SMEM>>>(p_y, w_proj, x, p_h, 1, nullptr, nullptr);
    gemm_mma<<<ggrid, 256, GEMM_SMEM>>>(p_h, enc_w0, nullptr, p_t0, 0, nullptr, nullptr);
    ln_kernel<<<MM, 128>>>(p_t0, ln1g, ln1b, p_ln);
    gemm_mma<<<ggrid, 256, GEMM_SMEM>>>(p_ln, enc_w1, p_h, p_t1, 2, nullptr, nullptr);
    ln_kernel<<<MM, 128>>>(p_t1, ln2g, ln2b, p_ln);
    gemm_mma<<<ggrid, 256, GEMM_SMEM>>>(p_ln, enc_w2, p_t1, p_t2, 2, nullptr, nullptr);
    final_kernel<<<MM, 256>>>(p_t2, enc_wo, ctemp, out);
}

// round 16
// speedup vs baseline: 1.2106x; 1.0763x over previous
#include <cuda_runtime.h>
#include <cuda_bf16.h>
#include <cuda_fp16.h>
#include <math.h>
#include <stdint.h>

// ---------------- problem constants ----------------
#define BB 2
#define TT 2048
#define CC 512
#define HH 8
#define DP 32
#define DH 64
#define MM (BB*TT)          // 4096 rows

// ---------------- scratch (no allocs allowed) ----------------
__device__ float g_wqk[512*512];
__device__ float g_qk [MM*512];
__device__ float g_v  [MM*CC];
__device__ float g_h  [MM*CC];
__device__ float g_t0 [MM*CC];
__device__ float g_ln [MM*CC];
__device__ float g_t1 [MM*CC];
__device__ float g_t2 [MM*CC];
__device__ float g_y  [MM*CC];
__device__ __half g_qh[BB*HH*TT*DP], g_ql[BB*HH*TT*DP];
__device__ __half g_kh[BB*HH*TT*DP], g_kl[BB*HH*TT*DP];
__device__ __half g_vh[MM*CC];

// ---------------- helpers ----------------
__device__ __forceinline__ uint32_t smem_u32(const void* p) {
    uint32_t a;
    asm("{ .reg .u64 t; cvta.to.shared.u64 t, %1; cvt.u32.u64 %0, t; }" : "=r"(a) : "l"(p));
    return a;
}
__device__ __forceinline__ void ldsm4(uint32_t* r, uint32_t addr) {
    asm volatile("ldmatrix.sync.aligned.m8n8.x4.shared.b16 {%0,%1,%2,%3}, [%4];"
        : "=r"(r[0]), "=r"(r[1]), "=r"(r[2]), "=r"(r[3]) : "r"(addr));
}
__device__ __forceinline__ void ldsm4t(uint32_t* r, uint32_t addr) {
    asm volatile("ldmatrix.sync.aligned.m8n8.x4.trans.shared.b16 {%0,%1,%2,%3}, [%4];"
        : "=r"(r[0]), "=r"(r[1]), "=r"(r[2]), "=r"(r[3]) : "r"(addr));
}
__device__ __forceinline__ void ldsm2(uint32_t* r, uint32_t addr) {
    asm volatile("ldmatrix.sync.aligned.m8n8.x2.shared.b16 {%0,%1}, [%2];"
        : "=r"(r[0]), "=r"(r[1]) : "r"(addr));
}
__device__ __forceinline__ void mma16816(float* d, const uint32_t* a, const uint32_t* b) {
    asm volatile("mma.sync.aligned.m16n8k16.row.col.f32.bf16.bf16.f32 "
        "{%0,%1,%2,%3}, {%4,%5,%6,%7}, {%8,%9}, {%0,%1,%2,%3};"
        : "+f"(d[0]), "+f"(d[1]), "+f"(d[2]), "+f"(d[3])
        : "r"(a[0]), "r"(a[1]), "r"(a[2]), "r"(a[3]), "r"(b[0]), "r"(b[1]));
}
__device__ __forceinline__ void mma16816h(float* d, const uint32_t* a, const uint32_t* b) {
    asm volatile("mma.sync.aligned.m16n8k16.row.col.f32.f16.f16.f32 "
        "{%0,%1,%2,%3}, {%4,%5,%6,%7}, {%8,%9}, {%0,%1,%2,%3};"
        : "+f"(d[0]), "+f"(d[1]), "+f"(d[2]), "+f"(d[3])
        : "r"(a[0]), "r"(a[1]), "r"(a[2]), "r"(a[3]), "r"(b[0]), "r"(b[1]));
}
__device__ __forceinline__ void split2(float x, float y, uint32_t& hi, uint32_t& lo) {
    __nv_bfloat162 h = __floats2bfloat162_rn(x, y);
    float2 hf = __bfloat1622float2(h);
    __nv_bfloat162 l = __floats2bfloat162_rn(x - hf.x, y - hf.y);
    hi = *(uint32_t*)&h; lo = *(uint32_t*)&l;
}
#define CP16(dst, src) \
    asm volatile("cp.async.cg.shared.global [%0], [%1], 16;" :: "r"(dst), "l"(src))
#define CP_COMMIT() asm volatile("cp.async.commit_group;" ::: "memory")
#define CP_WAIT1()  asm volatile("cp.async.wait_group 1;" ::: "memory")
#define CP_WAIT0()  asm volatile("cp.async.wait_group 0;" ::: "memory")

// ---------------- repack q/k projections into NT weight layout ----------------
__global__ void repack_kernel(const float* __restrict__ qp, const float* __restrict__ kp,
                              float* __restrict__ W) {
    int idx = blockIdx.x * 256 + threadIdx.x;
    if (idx >= 256*512) return;
    int n = idx >> 9, d = idx & 511;
    int h = n >> 5, o = n & 31;
    W[idx]            = qp[((h<<9)+d)*32 + o];
    W[(256<<9) + idx] = kp[((h<<9)+d)*32 + o];
}

// ---------------- bf16x3 mma.sync GEMM (R8/R12 proven config) ----------------
#define GPAD 40
#define OFF_AH 0
#define OFF_AL 5120
#define OFF_BH 10240
#define OFF_BL 15360
#define GSTG   20480

__global__ __launch_bounds__(256, 1)
void gemm_mma(const float* __restrict__ A, const float* __restrict__ W,
              const float* __restrict__ R, float* __restrict__ C, int mode,
              __half* __restrict__ Chi) {
    extern __shared__ __align__(16) char gsm[];
    __nv_bfloat16* s = (__nv_bfloat16*)gsm;
    uint32_t sb0 = smem_u32(s);

    int tid = threadIdx.x;
    int lane = tid & 31, wid = tid >> 5;
    int wm = wid >> 2, wn = wid & 3;
    int row0 = blockIdx.y * 128, col0 = blockIdx.x * 128;

    float acc[4][4][4];
#pragma unroll
    for (int mi = 0; mi < 4; mi++)
#pragma unroll
        for (int ni = 0; ni < 4; ni++)
#pragma unroll
            for (int e = 0; e < 4; e++) acc[mi][ni][e] = 0.f;

    float4 la[4], lb[4];
    int lrow[4], lc4[4];
#pragma unroll
    for (int it = 0; it < 4; it++) {
        int slot = it * 256 + tid;
        lrow[it] = slot >> 3;
        lc4[it]  = (slot & 7) << 2;
    }

#pragma unroll
    for (int it = 0; it < 4; it++) {
        la[it] = *(const float4*)&A[(size_t)(row0 + lrow[it]) * 512 + lc4[it]];
        lb[it] = *(const float4*)&W[(size_t)(col0 + lrow[it]) * 512 + lc4[it]];
    }
#pragma unroll
    for (int it = 0; it < 4; it++) {
        int base = lrow[it] * GPAD + lc4[it];
        uint2 h, l;
        split2(la[it].x, la[it].y, h.x, l.x); split2(la[it].z, la[it].w, h.y, l.y);
        *(uint2*)&s[OFF_AH + base] = h; *(uint2*)&s[OFF_AL + base] = l;
        split2(lb[it].x, lb[it].y, h.x, l.x); split2(lb[it].z, lb[it].w, h.y, l.y);
        *(uint2*)&s[OFF_BH + base] = h; *(uint2*)&s[OFF_BL + base] = l;
    }
    __syncthreads();

    for (int k = 0; k < 16; k++) {
        int cur = k & 1;
        if (k < 15) {
            int kc = (k + 1) * 32;
#pragma unroll
            for (int it = 0; it < 4; it++) {
                la[it] = *(const float4*)&A[(size_t)(row0 + lrow[it]) * 512 + kc + lc4[it]];
                lb[it] = *(const float4*)&W[(size_t)(col0 + lrow[it]) * 512 + kc + lc4[it]];
            }
        }
        uint32_t sb = sb0 + (uint32_t)cur * (GSTG * 2);
        int l16 = lane & 15;
        uint32_t arow = (uint32_t)(wm * 64 + (lane & 15)) * GPAD + (uint32_t)((lane >> 4) << 3);
        uint32_t brow = (uint32_t)(wn * 32 + (l16 & 7)) * GPAD + (uint32_t)((l16 >> 3) << 3);
#pragma unroll
        for (int ks = 0; ks < 2; ks++) {
            uint32_t a[4][4], bh[4][2], bl[4][2];
#pragma unroll
            for (int mi = 0; mi < 4; mi++)
                ldsm4(a[mi], sb + 2 * (OFF_AH + arow + (uint32_t)(mi * 16) * GPAD + ks * 16));
#pragma unroll
            for (int ni = 0; ni < 4; ni++) {
                uint32_t ba = sb + 2 * (brow + (uint32_t)(ni * 8) * GPAD + ks * 16);
                ldsm2(bh[ni], ba + 2 * OFF_BH);
                ldsm2(bl[ni], ba + 2 * OFF_BL);
            }
#pragma unroll
            for (int mi = 0; mi < 4; mi++)
#pragma unroll
                for (int ni = 0; ni < 4; ni++) mma16816(acc[mi][ni], a[mi], bh[ni]);
#pragma unroll
            for (int mi = 0; mi < 4; mi++)
#pragma unroll
                for (int ni = 0; ni < 4; ni++) mma16816(acc[mi][ni], a[mi], bl[ni]);
#pragma unroll
            for (int mi = 0; mi < 4; mi++)
                ldsm4(a[mi], sb + 2 * (OFF_AL + arow + (uint32_t)(mi * 16) * GPAD + ks * 16));
#pragma unroll
            for (int mi = 0; mi < 4; mi++)
#pragma unroll
                for (int ni = 0; ni < 4; ni++) mma16816(acc[mi][ni], a[mi], bh[ni]);
        }
        if (k < 15) {
            __nv_bfloat16* sn = s + (size_t)((k + 1) & 1) * GSTG;
#pragma unroll
            for (int it = 0; it < 4; it++) {
                int base = lrow[it] * GPAD + lc4[it];
                uint2 h, l;
                split2(la[it].x, la[it].y, h.x, l.x); split2(la[it].z, la[it].w, h.y, l.y);
                *(uint2*)&sn[OFF_AH + base] = h; *(uint2*)&sn[OFF_AL + base] = l;
                split2(lb[it].x, lb[it].y, h.x, l.x); split2(lb[it].z, lb[it].w, h.y, l.y);
                *(uint2*)&sn[OFF_BH + base] = h; *(uint2*)&sn[OFF_BL + base] = l;
            }
        }
        __syncthreads();
    }

    int gid = lane >> 2, tig = lane & 3;
#pragma unroll
    for (int mi = 0; mi < 4; mi++) {
#pragma unroll
        for (int ni = 0; ni < 4; ni++) {
            int rg = row0 + wm * 64 + mi * 16 + gid;
            int cg = col0 + wn * 32 + ni * 8 + tig * 2;
#pragma unroll
            for (int half = 0; half < 2; half++) {
                int r = rg + half * 8;
                float vx = acc[mi][ni][half * 2], vy = acc[mi][ni][half * 2 + 1];
                size_t gi = (size_t)r * 512 + cg;
                if (mode == 1) {
                    float2 rv = *(const float2*)&R[gi];
                    vx += rv.x; vy += rv.y;
                } else if (mode == 2) {
                    float2 rv = *(const float2*)&R[gi];
                    vx = rv.x + vx / (1.f + __expf(-vx));
                    vy = rv.y + vy / (1.f + __expf(-vy));
                }
                float2 ov; ov.x = vx; ov.y = vy;
                *(float2*)&C[gi] = ov;
                if (Chi) {
                    __half2 hh = __floats2half2_rn(vx, vy);
                    *(uint32_t*)&Chi[gi] = *(uint32_t*)&hh;
                }
            }
        }
    }
}

// ---------------- RoPE + gain (+ scale folded into q), f16 hi/lo outputs ----------------
__global__ void rope_kernel(const float* __restrict__ QK, const float* __restrict__ gain,
                            __half* __restrict__ Qh, __half* __restrict__ Ql,
                            __half* __restrict__ Kh, __half* __restrict__ Kl) {
    int bt = blockIdx.x;
    int t  = bt & (TT - 1);
    int b  = bt >> 11;
    int tid = threadIdx.x;
    int h = tid >> 4, i = tid & 15;
    float freq = powf(10000.f, -(float)i * (1.f / 16.f));
    float ang  = (float)t * freq;
    float c = cosf(ang), s = sinf(ang);
    const float* rowq = QK + (size_t)bt * 512 + h * 32;
    const float* rowk = rowq + 256;
    float g  = gain[h] * 0.17677669529663687f;
    float q1 = rowq[i], q2 = rowq[i + 16];
    float k1 = rowk[i], k2 = rowk[i + 16];
    float qa = (q1 * c - q2 * s) * g;
    float qb = (q2 * c + q1 * s) * g;
    float ka = (k1 * c - k2 * s);
    float kb = (k2 * c + k1 * s);
    size_t base = ((size_t)(b * HH + h) * TT + t) * DP;
    __half hh;
    hh = __float2half_rn(qa); Qh[base + i]      = hh; Ql[base + i]      = __float2half_rn(qa - __half2float(hh));
    hh = __float2half_rn(qb); Qh[base + i + 16] = hh; Ql[base + i + 16] = __float2half_rn(qb - __half2float(hh));
    hh = __float2half_rn(ka); Kh[base + i]      = hh; Kl[base + i]      = __float2half_rn(ka - __half2float(hh));
    hh = __float2half_rn(kb); Kh[base + i + 16] = hh; Kl[base + i + 16] = __float2half_rn(kb - __half2float(hh));
}

// ---------------- flash attention: 128-thr CTA (q-tile 64), occ 2, f16 ----------------
// smem per stage (halves): Kh[64][40]@0, Kl@2560, Vh[64][72]@5120 -> 9728 (19456 B)
#define FKP 40
#define FVP 72
#define SKH 0
#define SKL 2560
#define SVH 5120
#define FSTG 9728
#define L2E 1.4426950408889634f

__global__ __launch_bounds__(128, 2)
void flash_mma(const __half* __restrict__ Qh, const __half* __restrict__ Ql,
               const __half* __restrict__ Kh, const __half* __restrict__ Kl,
               const __half* __restrict__ Vh,
               const float* __restrict__ V, float* __restrict__ Y) {
    extern __shared__ __align__(16) __half fs[];
    uint32_t sb = smem_u32(fs);

    int b = blockIdx.z, h = blockIdx.y;
    int qt = (int)gridDim.x - 1 - (int)blockIdx.x;     // heavy blocks first
    int tid = threadIdx.x, lane = tid & 31, wid = tid >> 5;   // 4 warps
    int gid = lane >> 2, tig = lane & 3;
    int qrow0 = qt * 64;

    size_t bh = (size_t)(b * HH + h) * TT;
    const __half* Khg = Kh + bh * DP;
    const __half* Klg = Kl + bh * DP;
    const __half* Vhg = Vh + (size_t)b * TT * CC + h * DH;
    const float* Vb = V + (size_t)b * TT * CC + h * DH;

    // ---- stage Q (64x32 hi/lo) into stage-0 smem, grab fragments ----
#pragma unroll
    for (int it = 0; it < 4; it++) {
        int c = it * 128 + tid;                  // 512 chunks of 8 halves
        int row = (c & 255) >> 2, col = (c & 3) << 3;
        const __half* src = (c < 256) ? (Qh + (bh + qrow0 + row) * DP + col)
                                      : (Ql + (bh + qrow0 + row) * DP + col);
        uint32_t doff = (c < 256) ? (uint32_t)(row * FKP + col)
                                  : (uint32_t)(2560 + row * FKP + col);
        *(uint4*)&fs[doff] = *(const uint4*)src;
    }
    __syncthreads();
    uint32_t qfh[2][4], qfl[2][4];
    {
        uint32_t arow = (uint32_t)(wid * 16 + (lane & 15)) * FKP + (uint32_t)((lane >> 4) << 3);
#pragma unroll
        for (int ks = 0; ks < 2; ks++) {
            ldsm4(qfh[ks], sb + 2 * (arow + ks * 16));
            ldsm4(qfl[ks], sb + 2 * (2560 + arow + ks * 16));
        }
    }
    __syncthreads();

    float m0 = -1e30f, m1 = -1e30f, l0 = 0.f, l1 = 0.f;
    float o[8][4];
#pragma unroll
    for (int nt = 0; nt < 8; nt++)
#pragma unroll
        for (int e = 0; e < 4; e++) o[nt][e] = 0.f;

    int wmax = qrow0 + wid * 16 + 15;
    int ntiles = qt + 1;

    auto issue = [&](int t, int s) {
        uint32_t st = sb + 2 * (uint32_t)(s * FSTG);
        int j0 = t * 64;
#pragma unroll
        for (int it = 0; it < 8; it++) {
            int c = it * 128 + tid;              // 1024 chunks of 16B
            if (c < 512) {
                int row = (c & 255) >> 2, col = (c & 3) << 3;
                const __half* src = (c < 256) ? (Khg + (size_t)(j0 + row) * DP + col)
                                              : (Klg + (size_t)(j0 + row) * DP + col);
                uint32_t doff = (c < 256) ? (uint32_t)(SKH + row * FKP + col)
                                          : (uint32_t)(SKL + row * FKP + col);
                CP16(st + 2 * doff, src);
            } else {
                int cc = c - 512;                // 512 chunks: V hi 64x64
                int row = cc >> 3, col = (cc & 7) << 3;
                CP16(st + 2 * (uint32_t)(SVH + row * FVP + col),
                     Vhg + (size_t)(j0 + row) * CC + col);
            }
        }
    };

    issue(0, 0);
    CP_COMMIT();

    for (int t = 0; t < ntiles; t++) {
        int s = t & 1;
        if (t + 1 < ntiles) { issue(t + 1, s ^ 1); CP_COMMIT(); CP_WAIT1(); }
        else                { CP_WAIT0(); }
        __syncthreads();

        int j0 = t * 64;
        uint32_t stg = sb + 2 * (uint32_t)(s * FSTG);
        if (j0 <= wmax) {
            // ---- QK^T (f16 hi/lo, 3 terms) ----
            float sc[8][4];
#pragma unroll
            for (int nt = 0; nt < 8; nt++)
#pragma unroll
                for (int e = 0; e < 4; e++) sc[nt][e] = 0.f;
            uint32_t kbase = (uint32_t)(lane & 7) * FKP + (uint32_t)(((lane >> 3) & 3) << 3);
#pragma unroll
            for (int nt = 0; nt < 8; nt++) {
                uint32_t kbh[4], kbl[4];
                uint32_t ka = stg + 2 * (kbase + (uint32_t)(nt * 8) * FKP);
                ldsm4(kbh, ka + 2 * SKH);
                ldsm4(kbl, ka + 2 * SKL);
                mma16816h(sc[nt], qfh[0], kbh);
                mma16816h(sc[nt], qfh[1], kbh + 2);
                mma16816h(sc[nt], qfh[0], kbl);
                mma16816h(sc[nt], qfh[1], kbl + 2);
                mma16816h(sc[nt], qfl[0], kbh);
                mma16816h(sc[nt], qfl[1], kbh + 2);
            }
            // ---- causal mask ----
            if (j0 + 63 > qrow0 + wid * 16) {
                int r0 = qrow0 + wid * 16 + gid, r1 = r0 + 8;
#pragma unroll
                for (int nt = 0; nt < 8; nt++) {
                    int c = j0 + nt * 8 + tig * 2;
                    if (c > r0)     sc[nt][0] = -1e30f;
                    if (c + 1 > r0) sc[nt][1] = -1e30f;
                    if (c > r1)     sc[nt][2] = -1e30f;
                    if (c + 1 > r1) sc[nt][3] = -1e30f;
                }
            }
            // ---- online softmax (f16x2 exp2) ----
            float mx0 = -1e30f, mx1 = -1e30f;
#pragma unroll
            for (int nt = 0; nt < 8; nt++) {
                mx0 = fmaxf(mx0, fmaxf(sc[nt][0], sc[nt][1]));
                mx1 = fmaxf(mx1, fmaxf(sc[nt][2], sc[nt][3]));
            }
            mx0 = fmaxf(mx0, __shfl_xor_sync(~0u, mx0, 1));
            mx0 = fmaxf(mx0, __shfl_xor_sync(~0u, mx0, 2));
            mx1 = fmaxf(mx1, __shfl_xor_sync(~0u, mx1, 1));
            mx1 = fmaxf(mx1, __shfl_xor_sync(~0u, mx1, 2));
            float mn0 = fmaxf(m0, mx0), mn1 = fmaxf(m1, mx1);
            float cr0 = __expf(m0 - mn0), cr1 = __expf(m1 - mn1);
            m0 = mn0; m1 = mn1;
            uint32_t pa[8], pb[8];
            float ls0 = 0.f, ls1 = 0.f;
#pragma unroll
            for (int nt = 0; nt < 8; nt++) {
                __half2 e0 = h2exp2(__floats2half2_rn((sc[nt][0] - m0) * L2E,
                                                      (sc[nt][1] - m0) * L2E));
                __half2 e1 = h2exp2(__floats2half2_rn((sc[nt][2] - m1) * L2E,
                                                      (sc[nt][3] - m1) * L2E));
                pa[nt] = *(uint32_t*)&e0;
                pb[nt] = *(uint32_t*)&e1;
                float2 f0 = __half22float2(e0);
                float2 f1 = __half22float2(e1);
                ls0 += f0.x + f0.y;
                ls1 += f1.x + f1.y;
            }
            l0 = l0 * cr0 + ls0;
            l1 = l1 * cr1 + ls1;
#pragma unroll
            for (int nt = 0; nt < 8; nt++) {
                o[nt][0] *= cr0; o[nt][1] *= cr0;
                o[nt][2] *= cr1; o[nt][3] *= cr1;
            }
            // ---- P @ V (f16 p x f16 V hi only) ----
            uint32_t vbase = (uint32_t)(lane & 15) * FVP + (uint32_t)((lane >> 4) << 3);
#pragma unroll
            for (int kk = 0; kk < 4; kk++) {
                uint32_t af[4];
                af[0] = pa[2*kk];     af[1] = pb[2*kk];
                af[2] = pa[2*kk + 1]; af[3] = pb[2*kk + 1];
#pragma unroll
                for (int nv = 0; nv < 4; nv++) {
                    uint32_t vbh[4];
                    uint32_t va = stg + 2 * (SVH + vbase + (uint32_t)(kk * 16) * FVP + (uint32_t)(nv * 16));
                    ldsm4t(vbh, va);
                    mma16816h(o[2*nv],     af, vbh);
                    mma16816h(o[2*nv + 1], af, vbh + 2);
                }
            }
        }
        __syncthreads();
    }

    // ---- finalize ----
    l0 += __shfl_xor_sync(~0u, l0, 1); l0 += __shfl_xor_sync(~0u, l0, 2);
    l1 += __shfl_xor_sync(~0u, l1, 1); l1 += __shfl_xor_sync(~0u, l1, 2);
    float inv0 = 1.f / l0, inv1 = 1.f / l1;
#pragma unroll
    for (int nt = 0; nt < 8; nt++) {
        o[nt][0] *= inv0; o[nt][1] *= inv0;
        o[nt][2] *= inv1; o[nt][3] *= inv1;
    }
    int i0 = qrow0 + wid * 16 + gid, i1 = i0 + 8;
    float dot0 = 0.f, n20 = 0.f, dot1 = 0.f, n21 = 0.f;
#pragma unroll
    for (int nt = 0; nt < 8; nt++) {
        int d = nt * 8 + tig * 2;
        float2 v0 = *(const float2*)&Vb[(size_t)i0 * CC + d];
        float2 v1 = *(const float2*)&Vb[(size_t)i1 * CC + d];
        dot0 += o[nt][0] * v0.x + o[nt][1] * v0.y;
        n20  += v0.x * v0.x + v0.y * v0.y;
        dot1 += o[nt][2] * v1.x + o[nt][3] * v1.y;
        n21  += v1.x * v1.x + v1.y * v1.y;
    }
    dot0 += __shfl_xor_sync(~0u, dot0, 1); dot0 += __shfl_xor_sync(~0u, dot0, 2);
    n20  += __shfl_xor_sync(~0u, n20, 1);  n20  += __shfl_xor_sync(~0u, n20, 2);
    dot1 += __shfl_xor_sync(~0u, dot1, 1); dot1 += __shfl_xor_sync(~0u, dot1, 2);
    n21  += __shfl_xor_sync(~0u, n21, 1);  n21  += __shfl_xor_sync(~0u, n21, 2);
    float nr0 = fmaxf(sqrtf(n20), 1e-12f);
    float nr1 = fmaxf(sqrtf(n21), 1e-12f);
    dot0 /= (nr0 * nr0);
    dot1 /= (nr1 * nr1);
    float* Y0 = Y + (size_t)(b * TT + i0) * CC + h * DH;
    float* Y1 = Y + (size_t)(b * TT + i1) * CC + h * DH;
#pragma unroll
    for (int nt = 0; nt < 8; nt++) {
        int d = nt * 8 + tig * 2;
        float2 v0 = *(const float2*)&Vb[(size_t)i0 * CC + d];
        float2 v1 = *(const float2*)&Vb[(size_t)i1 * CC + d];
        float2 y0, y1;
        y0.x = o[nt][0] - dot0 * v0.x; y0.y = o[nt][1] - dot0 * v0.y;
        y1.x = o[nt][2] - dot1 * v1.x; y1.y = o[nt][3] - dot1 * v1.y;
        *(float2*)&Y0[d] = y0;
        *(float2*)&Y1[d] = y1;
    }
}

// ---------------- layernorm (row of 512) ----------------
__global__ void ln_kernel(const float* __restrict__ X, const float* __restrict__ g,
                          const float* __restrict__ bta, float* __restrict__ O) {
    int row = blockIdx.x;
    int t = threadIdx.x;
    __shared__ float red[4], red2[4];
    const float* xp = X + (size_t)row * 512;
    float4 v = *(const float4*)&xp[t * 4];
    float s = v.x + v.y + v.z + v.w;
#pragma unroll
    for (int off = 16; off; off >>= 1) s += __shfl_xor_sync(~0u, s, off);
    if ((t & 31) == 0) red[t >> 5] = s;
    __syncthreads();
    float mean = (red[0] + red[1] + red[2] + red[3]) * (1.f / 512.f);
    float dx = v.x - mean, dy = v.y - mean, dz = v.z - mean, dw = v.w - mean;
    float s2 = dx*dx + dy*dy + dz*dz + dw*dw;
#pragma unroll
    for (int off = 16; off; off >>= 1) s2 += __shfl_xor_sync(~0u, s2, off);
    if ((t & 31) == 0) red2[t >> 5] = s2;
    __syncthreads();
    float var = (red2[0] + red2[1] + red2[2] + red2[3]) * (1.f / 512.f);
    float rsv = rsqrtf(var + 1e-5f);
    float4 gg = *(const float4*)&g[t * 4];
    float4 bb = *(const float4*)&bta[t * 4];
    float4 ov;
    ov.x = dx * rsv * gg.x + bb.x;
    ov.y = dy * rsv * gg.y + bb.y;
    ov.z = dz * rsv * gg.z + bb.z;
    ov.w = dw * rsv * gg.w + bb.w;
    *(float4*)&O[(size_t)row * 512 + t * 4] = ov;
}

// ---------------- rms + out-proj (32) + tanh/temp ----------------
__global__ void final_kernel(const float* __restrict__ X, const float* __restrict__ Wout,
                             const float* __restrict__ ct, float* __restrict__ Z) {
    int row = blockIdx.x;
    int t = threadIdx.x;
    __shared__ __align__(16) float xs[512];
    __shared__ float red[8];
    __shared__ float pm[32][9];
    const float* xp = X + (size_t)row * 512;
    float2 v = *(const float2*)&xp[t * 2];
    float s2 = v.x * v.x + v.y * v.y;
#pragma unroll
    for (int off = 16; off; off >>= 1) s2 += __shfl_xor_sync(~0u, s2, off);
    if ((t & 31) == 0) red[t >> 5] = s2;
    __syncthreads();
    float tot = 0.f;
#pragma unroll
    for (int w = 0; w < 8; w++) tot += red[w];
    float rs = rsqrtf(tot * (1.f / 512.f) + 1e-6f);
    xs[t*2] = v.x * rs; xs[t*2+1] = v.y * rs;
    __syncthreads();
    int mi = t >> 3, seg = t & 7;
    const float* wrow = Wout + mi * 512 + seg * 64;
    const float* xseg = xs + seg * 64;
    float acc = 0.f;
#pragma unroll
    for (int d = 0; d < 64; d += 4) {
        float4 wv = *(const float4*)&wrow[d];
        acc += xseg[d]*wv.x + xseg[d+1]*wv.y + xseg[d+2]*wv.z + xseg[d+3]*wv.w;
    }
    pm[mi][seg] = acc;
    __syncthreads();
    if (t < 32) {
        float a = 0.f;
#pragma unroll
        for (int sgi = 0; sgi < 8; sgi++) a += pm[t][sgi];
        float cv = ct[t];
        float sp = (cv > 20.f) ? cv : log1pf(expf(cv));
        Z[(size_t)row * 32 + t] = tanhf(a / (sp + 1e-4f));
    }
}

// ---------------- launch ----------------
extern "C" void kernel_launch(void* const* d_in, const int* in_sizes, int n_in,
                              void* d_out, int out_size) {
    const float* x       = (const float*)d_in[0];
    const float* q_projs = (const float*)d_in[1];
    const float* k_projs = (const float*)d_in[2];
    const float* w_v     = (const float*)d_in[3];
    const float* w_proj  = (const float*)d_in[4];
    const float* q_gain  = (const float*)d_in[5];
    const float* enc_w0  = (const float*)d_in[6];
    const float* ln1g    = (const float*)d_in[7];
    const float* ln1b    = (const float*)d_in[8];
    const float* enc_w1  = (const float*)d_in[9];
    const float* ln2g    = (const float*)d_in[10];
    const float* ln2b    = (const float*)d_in[11];
    const float* enc_w2  = (const float*)d_in[12];
    const float* enc_wo  = (const float*)d_in[13];
    const float* ctemp   = (const float*)d_in[14];
    float* out = (float*)d_out;

    float *p_wqk, *p_qk, *p_v, *p_y, *p_h, *p_t0, *p_ln, *p_t1, *p_t2;
    __half *p_qh, *p_ql, *p_kh, *p_kl, *p_vh;
    cudaGetSymbolAddress((void**)&p_wqk, g_wqk);
    cudaGetSymbolAddress((void**)&p_qk,  g_qk);
    cudaGetSymbolAddress((void**)&p_v,   g_v);
    cudaGetSymbolAddress((void**)&p_y,   g_y);
    cudaGetSymbolAddress((void**)&p_h,   g_h);
    cudaGetSymbolAddress((void**)&p_t0,  g_t0);
    cudaGetSymbolAddress((void**)&p_ln,  g_ln);
    cudaGetSymbolAddress((void**)&p_t1,  g_t1);
    cudaGetSymbolAddress((void**)&p_t2,  g_t2);
    cudaGetSymbolAddress((void**)&p_qh,  g_qh);
    cudaGetSymbolAddress((void**)&p_ql,  g_ql);
    cudaGetSymbolAddress((void**)&p_kh,  g_kh);
    cudaGetSymbolAddress((void**)&p_kl,  g_kl);
    cudaGetSymbolAddress((void**)&p_vh,  g_vh);

    const int GEMM_SMEM  = 2 * GSTG * 2;   // 81920 B
    const int FLASH_SMEM = 2 * FSTG * 2;   // 38912 B
    cudaFuncSetAttribute(gemm_mma,  cudaFuncAttributeMaxDynamicSharedMemorySize, GEMM_SMEM);
    cudaFuncSetAttribute(flash_mma, cudaFuncAttributeMaxDynamicSharedMemorySize, FLASH_SMEM);

    dim3 ggrid(512 / 128, MM / 128);   // (4, 32)

    repack_kernel<<<512, 256>>>(q_projs, k_projs, p_wqk);
    gemm_mma<<<ggrid, 256, GEMM_SMEM>>>(x, p_wqk, nullptr, p_qk, 0, nullptr);
    rope_kernel<<<MM, 128>>>(p_qk, q_gain, p_qh, p_ql, p_kh, p_kl);
    gemm_mma<<<ggrid, 256, GEMM_SMEM>>>(x, w_v, nullptr, p_v, 0, p_vh);
    flash_mma<<<dim3(TT / 64, HH, BB), 128, FLASH_SMEM>>>(p_qh, p_ql, p_kh, p_kl,
                                                          p_vh, p_v, p_y);
    gemm_mma<<<ggrid, 256, GEMM_SMEM>>>(p_y, w_proj, x, p_h, 1, nullptr);
    gemm_mma<<<ggrid, 256, GEMM_SMEM>>>(p_h, enc_w0, nullptr, p_t0, 0, nullptr);
    ln_kernel<<<MM, 128>>>(p_t0, ln1g, ln1b, p_ln);
    gemm_mma<<<ggrid, 256, GEMM_SMEM>>>(p_ln, enc_w1, p_h, p_t1, 2, nullptr);
    ln_kernel<<<MM, 128>>>(p_t1, ln2g, ln2b, p_ln);
    gemm_mma<<<ggrid, 256, GEMM_SMEM>>>(p_ln, enc_w2, p_t1, p_t2, 2, nullptr);
    final_kernel<<<MM, 256>>>(p_t2, enc_wo, ctemp, out);
}